// round 1
// baseline (speedup 1.0000x reference)
#include <cuda_runtime.h>
#include <math.h>

#define S     512
#define E     256
#define H2    512
#define HC    1024
#define VOCAB 50257
#define GRID  148
#define NT    256
#define ROWS_PER_CTA 340   // ceil(50257/148)

// ---------------- device scratch (static globals; no allocation) ----------------
__device__ float g_emb[S*E];
__device__ int   g_mask[S];
__device__ float g_ehf[2][E];
__device__ float g_ehb[2][E];
__device__ float g_outf[S*E];
__device__ float g_outb[S*E];
__device__ float g_encT[H2*S];     // [k][s], masked encoder outputs (transposed)
__device__ float g_A[S*H2];        // enc_masked @ attn_W
__device__ float g_dvec[S];        // enc_masked @ attn_b
__device__ float g_enchid[H2];
__device__ float g_dh[2][H2];      // decoder h, double buffered
__device__ float g_scores[S];
__device__ float g_ctx[H2];
__device__ float g_z[HC];
__device__ float g_pval[GRID];
__device__ int   g_pidx[GRID];
__device__ unsigned g_arrive;
__device__ unsigned g_epoch;

__global__ void init_kernel() { g_arrive = 0u; g_epoch = 0u; }

__device__ __forceinline__ float sigf(float x) { return 1.f / (1.f + expf(-x)); }

// grid-wide barrier: release (fence + relaxed add) / acquire (ld.acquire spin)
__device__ __forceinline__ void gbar(unsigned &nb) {
    __syncthreads();
    nb++;
    if (threadIdx.x == 0) {
        __threadfence();
        unsigned t = atomicAdd(&g_arrive, 1u);
        if (t == GRID - 1u) {
            g_arrive = 0u;
            __threadfence();
            atomicAdd(&g_epoch, 1u);
        } else {
            unsigned e;
            do {
                asm volatile("ld.acquire.gpu.u32 %0, [%1];" : "=r"(e) : "l"(&g_epoch));
            } while (e < nb);
        }
    }
    __syncthreads();
}

__global__ void __launch_bounds__(NT, 1) seq2seq_kernel(
    const int*   __restrict__ tokens,
    const float* __restrict__ enc_emb,
    const float* __restrict__ dec_emb,
    const float* __restrict__ eWi_f, const float* __restrict__ eWh_f, const float* __restrict__ eb_f,
    const float* __restrict__ eWi_b, const float* __restrict__ eWh_b, const float* __restrict__ eb_b,
    const float* __restrict__ dWi,   const float* __restrict__ dWh,   const float* __restrict__ db,
    const float* __restrict__ attn_W, const float* __restrict__ attn_b,
    const float* __restrict__ W_W,    const float* __restrict__ W_b,
    const float* __restrict__ lin_W,  const float* __restrict__ lin_b,
    float* __restrict__ out, int sent_off)
{
    __shared__ float s_a[HC];
    __shared__ float s_b[H2];
    __shared__ float s_red[32];
    __shared__ int   s_redi[8];
    __shared__ float s_ec[4];
    __shared__ float s_dc[4];
    __shared__ int   s_word;

    const int cta = blockIdx.x, tid = threadIdx.x;
    const int warp = tid >> 5, lane = tid & 31;
    unsigned nb = 0;
    float* out_logits = out + (sent_off ? (S + 1) : 0);

    // ---------- setup: embeddings, mask, zero initial LSTM states ----------
    for (int idx = cta * NT + tid; idx < S * E; idx += GRID * NT) {
        int t = idx / E, k = idx - t * E;
        g_emb[idx] = fmaxf(enc_emb[(size_t)tokens[t] * E + k], 0.f);
    }
    for (int idx = cta * NT + tid; idx < S; idx += GRID * NT) g_mask[idx] = tokens[idx] > 0;
    for (int idx = cta * NT + tid; idx < E; idx += GRID * NT) { g_ehf[1][idx] = 0.f; g_ehb[1][idx] = 0.f; }
    if (tid < 4) { s_ec[tid] = 0.f; s_dc[tid] = 0.f; }
    gbar(nb);

    // ---------- encoder BiLSTM: CTAs 0..63 fwd, 64..127 bwd ----------
    if (cta < 128) {
        const int dir   = cta >> 6;
        const int ubase = (cta & 63) * 4;
        const float* Wi = dir ? eWi_b : eWi_f;
        const float* Wh = dir ? eWh_b : eWh_f;
        const float* bb = dir ? eb_b  : eb_f;
        const int rl = tid >> 4, l16 = tid & 15;
        const int u = rl >> 2, gg = rl & 3;
        const int unit = ubase + u;
        const int row  = gg * E + unit;
        const float* wi = Wi + row * E;
        const float* wh = Wh + row * E;
        const float brow = bb[row];
        for (int t = 0; t < S; t++) {
            const int xt = dir ? (S - 1 - t) : t;
            const float* hrd = dir ? g_ehb[(t ^ 1) & 1] : g_ehf[(t ^ 1) & 1];
            for (int i = tid; i < E; i += NT) { s_a[i] = g_emb[xt * E + i]; s_b[i] = hrd[i]; }
            __syncthreads();
            float acc = 0.f;
            #pragma unroll 4
            for (int k = l16; k < E; k += 16) acc += wi[k] * s_a[k];
            #pragma unroll 4
            for (int k = l16; k < E; k += 16) acc += wh[k] * s_b[k];
            #pragma unroll
            for (int o = 8; o; o >>= 1) acc += __shfl_down_sync(0xffffffffu, acc, o, 16);
            if (l16 == 0) s_red[rl] = acc + brow;
            __syncthreads();
            if (tid < 4) {
                float gi = s_red[tid*4+0], gf = s_red[tid*4+1], gc = s_red[tid*4+2], go = s_red[tid*4+3];
                float c = sigf(gf) * s_ec[tid] + sigf(gi) * tanhf(gc);
                float h = sigf(go) * tanhf(c);
                s_ec[tid] = c;
                int uj = ubase + tid;
                (dir ? g_ehb[t & 1] : g_ehf[t & 1])[uj] = h;
                (dir ? g_outb : g_outf)[xt * E + uj]   = h;
            }
            gbar(nb);
        }
    } else {
        for (int t = 0; t < S; t++) gbar(nb);
    }

    // ---------- setup2: encT, A = enc_m @ attn_W, d = enc_m @ attn_b, enc_hidden ----------
    for (int idx = cta * NT + tid; idx < H2 * S; idx += GRID * NT) {
        int k = idx / S, s = idx - k * S;
        float v = (k < E) ? g_outf[s * E + k] : g_outb[s * E + (k - E)];
        g_encT[idx] = g_mask[s] ? v : 0.f;
    }
    for (int s = cta; s < S; s += GRID) {
        float m = g_mask[s] ? 1.f : 0.f;
        for (int j = tid; j < H2; j += NT)
            s_a[j] = ((j < E) ? g_outf[s * E + j] : g_outb[s * E + j - E]) * m;
        __syncthreads();
        for (int k = tid; k < H2; k += NT) {
            float acc = 0.f;
            #pragma unroll 4
            for (int j = 0; j < H2; j++) acc += s_a[j] * attn_W[j * H2 + k];
            g_A[s * H2 + k] = acc;
        }
        if (tid == 0) {
            float acc = 0.f;
            for (int j = 0; j < H2; j++) acc += s_a[j] * attn_b[j];
            g_dvec[s] = acc;
        }
        __syncthreads();
    }
    if (cta == 0) {
        for (int j = tid; j < E; j += NT) {
            float hf = g_outf[(S - 1) * E + j];
            float hb = g_outb[0 * E + j];
            g_enchid[j]     = hf; g_enchid[E + j] = hb;
            g_dh[1][j]      = hf; g_dh[1][E + j]  = hb;
        }
        if (tid == 0 && sent_off) out[0] = 1.0f;   // SOS
    }
    if (tid == 0) s_word = 1;                       // SOS
    gbar(nb);

    // ---------- autoregressive decode, 512 steps ----------
    for (int t = 0; t < S; t++) {
        // Phase G: decoder LSTM gates -> h, c (CTAs 0..127, 4 units each)
        if (cta < 128) {
            const int w = s_word;
            for (int i = tid; i < H2; i += NT) {
                s_a[i]      = fmaxf(dec_emb[(size_t)w * H2 + i], 0.f);
                s_a[H2 + i] = g_enchid[i];
                s_b[i]      = g_dh[(t ^ 1) & 1][i];
            }
            __syncthreads();
            const int rl = tid >> 4, l16 = tid & 15;
            const int u = rl >> 2, gg = rl & 3;
            const int unit = (cta << 2) + u;
            const int row  = gg * H2 + unit;
            float acc = 0.f;
            const float* wi = dWi + (size_t)row * HC;
            #pragma unroll 4
            for (int k = l16; k < HC; k += 16) acc += wi[k] * s_a[k];
            const float* wh = dWh + (size_t)row * H2;
            #pragma unroll 4
            for (int k = l16; k < H2; k += 16) acc += wh[k] * s_b[k];
            #pragma unroll
            for (int o = 8; o; o >>= 1) acc += __shfl_down_sync(0xffffffffu, acc, o, 16);
            if (l16 == 0) s_red[rl] = acc + db[row];
            __syncthreads();
            if (tid < 4) {
                float gi = s_red[tid*4+0], gf = s_red[tid*4+1], gc = s_red[tid*4+2], go = s_red[tid*4+3];
                float c = sigf(gf) * s_dc[tid] + sigf(gi) * tanhf(gc);
                float h = sigf(go) * tanhf(c);
                s_dc[tid] = c;
                g_dh[t & 1][(cta << 2) + tid] = h;
            }
        }
        gbar(nb);

        // Phase S: scores = A @ h + d  (warp-per-output, warps 0..511)
        {
            const int gw = cta * 8 + warp;
            if (gw < S) {
                const float* Ar = g_A + gw * H2;
                const float* hv = g_dh[t & 1];
                float acc = 0.f;
                #pragma unroll 4
                for (int k = lane; k < H2; k += 32) acc += Ar[k] * hv[k];
                #pragma unroll
                for (int o = 16; o; o >>= 1) acc += __shfl_down_sync(0xffffffffu, acc, o);
                if (lane == 0) {
                    float sc = acc + g_dvec[gw];
                    g_scores[gw] = g_mask[gw] ? sc : -INFINITY;
                }
            }
        }
        gbar(nb);

        // Phase C: per-CTA redundant softmax + context (CTAs 0..63)
        if (cta < 64) {
            for (int i = tid; i < S; i += NT) s_b[i] = g_scores[i];
            __syncthreads();
            float m = -INFINITY;
            for (int i = tid; i < S; i += NT) m = fmaxf(m, s_b[i]);
            #pragma unroll
            for (int o = 16; o; o >>= 1) m = fmaxf(m, __shfl_down_sync(0xffffffffu, m, o));
            if (lane == 0) s_red[warp] = m;
            __syncthreads();
            if (tid == 0) {
                float mm = s_red[0];
                for (int i = 1; i < 8; i++) mm = fmaxf(mm, s_red[i]);
                s_red[16] = mm;
            }
            __syncthreads();
            const float mx = s_red[16];
            float sum = 0.f;
            for (int i = tid; i < S; i += NT) {
                float e = (mx == -INFINITY) ? 0.f : expf(s_b[i] - mx);
                s_b[i] = e; sum += e;
            }
            #pragma unroll
            for (int o = 16; o; o >>= 1) sum += __shfl_down_sync(0xffffffffu, sum, o);
            if (lane == 0) s_red[warp] = sum;
            __syncthreads();
            if (tid == 0) {
                float ss = 0.f;
                for (int i = 0; i < 8; i++) ss += s_red[i];
                s_red[17] = (ss > 0.f) ? 1.f / ss : 0.f;
            }
            __syncthreads();
            const float inv = s_red[17];
            for (int i = tid; i < S; i += NT) s_b[i] *= inv;
            __syncthreads();
            const int gw = cta * 8 + warp;                // 0..511
            const float* et = g_encT + (size_t)gw * S;
            float acc = 0.f;
            #pragma unroll 4
            for (int s2 = lane; s2 < S; s2 += 32) acc += s_b[s2] * et[s2];
            #pragma unroll
            for (int o = 16; o; o >>= 1) acc += __shfl_down_sync(0xffffffffu, acc, o);
            if (lane == 0) g_ctx[gw] = acc;
        }
        gbar(nb);

        // Phase Z: z = [h, ctx] @ W_W^T + W_b  (warps 0..1023)
        {
            const int gw = cta * 8 + warp;
            if (gw < HC) {
                const float* ww = W_W + (size_t)gw * HC;
                const float* hv = g_dh[t & 1];
                float acc = 0.f;
                #pragma unroll 4
                for (int k = lane; k < HC; k += 32) {
                    float hk = (k < H2) ? hv[k] : g_ctx[k - H2];
                    acc += ww[k] * hk;
                }
                #pragma unroll
                for (int o = 16; o; o >>= 1) acc += __shfl_down_sync(0xffffffffu, acc, o);
                if (lane == 0) g_z[gw] = acc + W_b[gw];
            }
        }
        gbar(nb);

        // Phase L: logits = z @ lin_W^T + lin_b  (206 MB streamed, HBM-bound)
        {
            for (int i = tid; i < HC; i += NT) s_a[i] = g_z[i];
            __syncthreads();
            const float4* z4 = (const float4*)s_a;
            const int r0 = cta * ROWS_PER_CTA;
            const int r1 = min(VOCAB, r0 + ROWS_PER_CTA);
            float bv = -INFINITY; int bi = 0;
            float* olog = out_logits + (size_t)t * VOCAB;
            int r = r0 + warp;
            for (; r + 8 < r1; r += 16) {                 // 2-row unroll for MLP
                const float4* w0 = (const float4*)(lin_W + (size_t)r * HC);
                const float4* w1 = (const float4*)(lin_W + (size_t)(r + 8) * HC);
                float a0 = 0.f, a1 = 0.f;
                #pragma unroll
                for (int i = 0; i < 8; i++) {
                    float4 zz = z4[lane + 32 * i];
                    float4 x0 = w0[lane + 32 * i];
                    float4 x1 = w1[lane + 32 * i];
                    a0 += x0.x*zz.x + x0.y*zz.y + x0.z*zz.z + x0.w*zz.w;
                    a1 += x1.x*zz.x + x1.y*zz.y + x1.z*zz.z + x1.w*zz.w;
                }
                #pragma unroll
                for (int o = 16; o; o >>= 1) {
                    a0 += __shfl_down_sync(0xffffffffu, a0, o);
                    a1 += __shfl_down_sync(0xffffffffu, a1, o);
                }
                if (lane == 0) {
                    float v0 = a0 + lin_b[r];     olog[r]     = v0;
                    float v1 = a1 + lin_b[r + 8]; olog[r + 8] = v1;
                    if (v0 > bv || (v0 == bv && r     < bi)) { bv = v0; bi = r;     }
                    if (v1 > bv || (v1 == bv && r + 8 < bi)) { bv = v1; bi = r + 8; }
                }
            }
            for (; r < r1; r += 8) {
                const float4* w0 = (const float4*)(lin_W + (size_t)r * HC);
                float a0 = 0.f;
                #pragma unroll
                for (int i = 0; i < 8; i++) {
                    float4 zz = z4[lane + 32 * i];
                    float4 x0 = w0[lane + 32 * i];
                    a0 += x0.x*zz.x + x0.y*zz.y + x0.z*zz.z + x0.w*zz.w;
                }
                #pragma unroll
                for (int o = 16; o; o >>= 1) a0 += __shfl_down_sync(0xffffffffu, a0, o);
                if (lane == 0) {
                    float v0 = a0 + lin_b[r]; olog[r] = v0;
                    if (v0 > bv || (v0 == bv && r < bi)) { bv = v0; bi = r; }
                }
            }
            __syncthreads();
            if (lane == 0) { s_red[warp] = bv; s_redi[warp] = bi; }
            __syncthreads();
            if (tid == 0) {
                float v = s_red[0]; int ii = s_redi[0];
                for (int i = 1; i < 8; i++)
                    if (s_red[i] > v || (s_red[i] == v && s_redi[i] < ii)) { v = s_red[i]; ii = s_redi[i]; }
                g_pval[cta] = v; g_pidx[cta] = ii;
            }
        }
        gbar(nb);

        // Phase R: redundant global argmax reduce -> next word (no barrier needed)
        if (tid == 0) {
            float v = g_pval[0]; int ii = g_pidx[0];
            for (int i = 1; i < GRID; i++) {
                float pv = g_pval[i];
                if (pv > v) { v = pv; ii = g_pidx[i]; }
            }
            s_word = ii;
            if (cta == 0 && sent_off) out[1 + t] = (float)ii;
        }
        __syncthreads();
    }
}

extern "C" void kernel_launch(void* const* d_in, const int* in_sizes, int n_in,
                              void* d_out, int out_size)
{
    const int*   tokens  = (const int*)  d_in[0];
    // d_in[1] = trg_seqs (unused by forward)
    const float* enc_emb = (const float*)d_in[2];
    const float* dec_emb = (const float*)d_in[3];
    const float* eWi_f   = (const float*)d_in[4];
    const float* eWh_f   = (const float*)d_in[5];
    const float* eb_f    = (const float*)d_in[6];
    const float* eWi_b   = (const float*)d_in[7];
    const float* eWh_b   = (const float*)d_in[8];
    const float* eb_b    = (const float*)d_in[9];
    const float* dWi     = (const float*)d_in[10];
    const float* dWh     = (const float*)d_in[11];
    const float* db      = (const float*)d_in[12];
    const float* attn_W  = (const float*)d_in[13];
    const float* attn_b  = (const float*)d_in[14];
    const float* W_W     = (const float*)d_in[15];
    const float* W_b     = (const float*)d_in[16];
    const float* lin_W   = (const float*)d_in[17];
    const float* lin_b   = (const float*)d_in[18];

    // sentence (S+1 as float) + logits (S*V), or logits-only fallback
    long long need_full = (long long)(S + 1) + (long long)S * VOCAB;
    int sent_off = ((long long)out_size >= need_full) ? 1 : 0;

    init_kernel<<<1, 1>>>();
    seq2seq_kernel<<<GRID, NT>>>(tokens, enc_emb, dec_emb,
                                 eWi_f, eWh_f, eb_f, eWi_b, eWh_b, eb_b,
                                 dWi, dWh, db, attn_W, attn_b, W_W, W_b,
                                 lin_W, lin_b, (float*)d_out, sent_off);
}

// round 2
// speedup vs baseline: 1.0023x; 1.0023x over previous
#include <cuda_runtime.h>
#include <math.h>

#define S     512
#define E     256
#define H2    512
#define HC    1024
#define VOCAB 50257
#define GRID  148
#define NT    256
#define ROWS_PER_CTA 340   // ceil(50257/148)

// ---------------- device scratch (static globals; no allocation) ----------------
__device__ float g_emb[S*E];
__device__ int   g_mask[S];
__device__ float g_ehf[2][E];
__device__ float g_ehb[2][E];
__device__ float g_outf[S*E];
__device__ float g_outb[S*E];
__device__ float g_encT[H2*S];     // [k][s], masked encoder outputs (transposed)
__device__ float g_A[S*H2];        // enc_masked @ attn_W
__device__ float g_dvec[S];        // enc_masked @ attn_b
__device__ float g_enchid[H2];
__device__ float g_dh[2][H2];      // decoder h, double buffered
__device__ float g_scores[S];
__device__ float g_ctx[H2];
__device__ float g_z[HC];
__device__ float g_pval[GRID];
__device__ int   g_pidx[GRID];
__device__ unsigned g_arrive;
__device__ unsigned g_epoch;

__global__ void init_kernel() { g_arrive = 0u; g_epoch = 0u; }

__device__ __forceinline__ float sigf(float x) { return 1.f / (1.f + expf(-x)); }

// grid-wide barrier: release (fence + relaxed add) / acquire (ld.acquire spin)
__device__ __forceinline__ void gbar(unsigned &nb) {
    __syncthreads();
    nb++;
    if (threadIdx.x == 0) {
        __threadfence();
        unsigned t = atomicAdd(&g_arrive, 1u);
        if (t == GRID - 1u) {
            g_arrive = 0u;
            __threadfence();
            atomicAdd(&g_epoch, 1u);
        } else {
            unsigned e;
            do {
                asm volatile("ld.acquire.gpu.u32 %0, [%1];" : "=r"(e) : "l"(&g_epoch));
            } while (e < nb);
        }
    }
    __syncthreads();
}

__global__ void __launch_bounds__(NT, 1) seq2seq_kernel(
    const int*   __restrict__ tokens,
    const float* __restrict__ enc_emb,
    const float* __restrict__ dec_emb,
    const float* __restrict__ eWi_f, const float* __restrict__ eWh_f, const float* __restrict__ eb_f,
    const float* __restrict__ eWi_b, const float* __restrict__ eWh_b, const float* __restrict__ eb_b,
    const float* __restrict__ dWi,   const float* __restrict__ dWh,   const float* __restrict__ db,
    const float* __restrict__ attn_W, const float* __restrict__ attn_b,
    const float* __restrict__ W_W,    const float* __restrict__ W_b,
    const float* __restrict__ lin_W,  const float* __restrict__ lin_b,
    float* __restrict__ out, int sent_off)
{
    __shared__ float s_a[HC];
    __shared__ float s_b[H2];
    __shared__ float s_red[32];
    __shared__ int   s_redi[8];
    __shared__ float s_ec[4];
    __shared__ float s_dc[4];
    __shared__ int   s_word;

    const int cta = blockIdx.x, tid = threadIdx.x;
    const int warp = tid >> 5, lane = tid & 31;
    unsigned nb = 0;
    float* out_logits = out + (sent_off ? (S + 1) : 0);

    // ---------- setup: embeddings, mask, zero initial LSTM states ----------
    for (int idx = cta * NT + tid; idx < S * E; idx += GRID * NT) {
        int t = idx / E, k = idx - t * E;
        g_emb[idx] = fmaxf(enc_emb[(size_t)tokens[t] * E + k], 0.f);
    }
    for (int idx = cta * NT + tid; idx < S; idx += GRID * NT) g_mask[idx] = tokens[idx] > 0;
    for (int idx = cta * NT + tid; idx < E; idx += GRID * NT) { g_ehf[1][idx] = 0.f; g_ehb[1][idx] = 0.f; }
    if (tid < 4) { s_ec[tid] = 0.f; s_dc[tid] = 0.f; }
    gbar(nb);

    // ---------- encoder BiLSTM: CTAs 0..63 fwd, 64..127 bwd ----------
    if (cta < 128) {
        const int dir   = cta >> 6;
        const int ubase = (cta & 63) * 4;
        const float* Wi = dir ? eWi_b : eWi_f;
        const float* Wh = dir ? eWh_b : eWh_f;
        const float* bb = dir ? eb_b  : eb_f;
        const int rl = tid >> 4, l16 = tid & 15;
        const int u = rl >> 2, gg = rl & 3;
        const int unit = ubase + u;
        const int row  = gg * E + unit;
        const float* wi = Wi + row * E;
        const float* wh = Wh + row * E;
        const float brow = bb[row];
        for (int t = 0; t < S; t++) {
            const int xt = dir ? (S - 1 - t) : t;
            const float* hrd = dir ? g_ehb[(t ^ 1) & 1] : g_ehf[(t ^ 1) & 1];
            for (int i = tid; i < E; i += NT) { s_a[i] = g_emb[xt * E + i]; s_b[i] = hrd[i]; }
            __syncthreads();
            float acc = 0.f;
            #pragma unroll 4
            for (int k = l16; k < E; k += 16) acc += wi[k] * s_a[k];
            #pragma unroll 4
            for (int k = l16; k < E; k += 16) acc += wh[k] * s_b[k];
            #pragma unroll
            for (int o = 8; o; o >>= 1) acc += __shfl_down_sync(0xffffffffu, acc, o, 16);
            if (l16 == 0) s_red[rl] = acc + brow;
            __syncthreads();
            if (tid < 4) {
                float gi = s_red[tid*4+0], gf = s_red[tid*4+1], gc = s_red[tid*4+2], go = s_red[tid*4+3];
                float c = sigf(gf) * s_ec[tid] + sigf(gi) * tanhf(gc);
                float h = sigf(go) * tanhf(c);
                s_ec[tid] = c;
                int uj = ubase + tid;
                (dir ? g_ehb[t & 1] : g_ehf[t & 1])[uj] = h;
                (dir ? g_outb : g_outf)[xt * E + uj]   = h;
            }
            gbar(nb);
        }
    } else {
        for (int t = 0; t < S; t++) gbar(nb);
    }

    // ---------- setup2: encT, A = enc_m @ attn_W, d = enc_m @ attn_b, enc_hidden ----------
    for (int idx = cta * NT + tid; idx < H2 * S; idx += GRID * NT) {
        int k = idx / S, s = idx - k * S;
        float v = (k < E) ? g_outf[s * E + k] : g_outb[s * E + (k - E)];
        g_encT[idx] = g_mask[s] ? v : 0.f;
    }
    for (int s = cta; s < S; s += GRID) {
        float m = g_mask[s] ? 1.f : 0.f;
        for (int j = tid; j < H2; j += NT)
            s_a[j] = ((j < E) ? g_outf[s * E + j] : g_outb[s * E + j - E]) * m;
        __syncthreads();
        for (int k = tid; k < H2; k += NT) {
            float acc = 0.f;
            #pragma unroll 4
            for (int j = 0; j < H2; j++) acc += s_a[j] * attn_W[j * H2 + k];
            g_A[s * H2 + k] = acc;
        }
        if (tid == 0) {
            float acc = 0.f;
            for (int j = 0; j < H2; j++) acc += s_a[j] * attn_b[j];
            g_dvec[s] = acc;
        }
        __syncthreads();
    }
    if (cta == 0) {
        for (int j = tid; j < E; j += NT) {
            float hf = g_outf[(S - 1) * E + j];
            float hb = g_outb[0 * E + j];
            g_enchid[j]     = hf; g_enchid[E + j] = hb;
            g_dh[1][j]      = hf; g_dh[1][E + j]  = hb;
        }
        if (tid == 0 && sent_off) out[0] = 1.0f;   // SOS
    }
    if (tid == 0) s_word = 1;                       // SOS
    gbar(nb);

    // ---------- autoregressive decode, 512 steps ----------
    for (int t = 0; t < S; t++) {
        // Phase G: decoder LSTM gates -> h, c (CTAs 0..127, 4 units each)
        if (cta < 128) {
            const int w = s_word;
            for (int i = tid; i < H2; i += NT) {
                s_a[i]      = fmaxf(dec_emb[(size_t)w * H2 + i], 0.f);
                s_a[H2 + i] = g_enchid[i];
                s_b[i]      = g_dh[(t ^ 1) & 1][i];
            }
            __syncthreads();
            const int rl = tid >> 4, l16 = tid & 15;
            const int u = rl >> 2, gg = rl & 3;
            const int unit = (cta << 2) + u;
            const int row  = gg * H2 + unit;
            float acc = 0.f;
            const float* wi = dWi + (size_t)row * HC;
            #pragma unroll 4
            for (int k = l16; k < HC; k += 16) acc += wi[k] * s_a[k];
            const float* wh = dWh + (size_t)row * H2;
            #pragma unroll 4
            for (int k = l16; k < H2; k += 16) acc += wh[k] * s_b[k];
            #pragma unroll
            for (int o = 8; o; o >>= 1) acc += __shfl_down_sync(0xffffffffu, acc, o, 16);
            if (l16 == 0) s_red[rl] = acc + db[row];
            __syncthreads();
            if (tid < 4) {
                float gi = s_red[tid*4+0], gf = s_red[tid*4+1], gc = s_red[tid*4+2], go = s_red[tid*4+3];
                float c = sigf(gf) * s_dc[tid] + sigf(gi) * tanhf(gc);
                float h = sigf(go) * tanhf(c);
                s_dc[tid] = c;
                g_dh[t & 1][(cta << 2) + tid] = h;
            }
        }
        gbar(nb);

        // Phase S: scores = A @ h + d  (warp-per-output, warps 0..511)
        {
            const int gw = cta * 8 + warp;
            if (gw < S) {
                const float* Ar = g_A + gw * H2;
                const float* hv = g_dh[t & 1];
                float acc = 0.f;
                #pragma unroll 4
                for (int k = lane; k < H2; k += 32) acc += Ar[k] * hv[k];
                #pragma unroll
                for (int o = 16; o; o >>= 1) acc += __shfl_down_sync(0xffffffffu, acc, o);
                if (lane == 0) {
                    float sc = acc + g_dvec[gw];
                    g_scores[gw] = g_mask[gw] ? sc : -INFINITY;
                }
            }
        }
        gbar(nb);

        // Phase C: per-CTA redundant softmax + context (CTAs 0..63)
        if (cta < 64) {
            for (int i = tid; i < S; i += NT) s_b[i] = g_scores[i];
            __syncthreads();
            float m = -INFINITY;
            for (int i = tid; i < S; i += NT) m = fmaxf(m, s_b[i]);
            #pragma unroll
            for (int o = 16; o; o >>= 1) m = fmaxf(m, __shfl_down_sync(0xffffffffu, m, o));
            if (lane == 0) s_red[warp] = m;
            __syncthreads();
            if (tid == 0) {
                float mm = s_red[0];
                for (int i = 1; i < 8; i++) mm = fmaxf(mm, s_red[i]);
                s_red[16] = mm;
            }
            __syncthreads();
            const float mx = s_red[16];
            float sum = 0.f;
            for (int i = tid; i < S; i += NT) {
                float e = (mx == -INFINITY) ? 0.f : expf(s_b[i] - mx);
                s_b[i] = e; sum += e;
            }
            #pragma unroll
            for (int o = 16; o; o >>= 1) sum += __shfl_down_sync(0xffffffffu, sum, o);
            if (lane == 0) s_red[warp] = sum;
            __syncthreads();
            if (tid == 0) {
                float ss = 0.f;
                for (int i = 0; i < 8; i++) ss += s_red[i];
                s_red[17] = (ss > 0.f) ? 1.f / ss : 0.f;
            }
            __syncthreads();
            const float inv = s_red[17];
            for (int i = tid; i < S; i += NT) s_b[i] *= inv;
            __syncthreads();
            const int gw = cta * 8 + warp;                // 0..511
            const float* et = g_encT + (size_t)gw * S;
            float acc = 0.f;
            #pragma unroll 4
            for (int s2 = lane; s2 < S; s2 += 32) acc += s_b[s2] * et[s2];
            #pragma unroll
            for (int o = 16; o; o >>= 1) acc += __shfl_down_sync(0xffffffffu, acc, o);
            if (lane == 0) g_ctx[gw] = acc;
        }
        gbar(nb);

        // Phase Z: z = [h, ctx] @ W_W^T + W_b  (warps 0..1023)
        {
            const int gw = cta * 8 + warp;
            if (gw < HC) {
                const float* ww = W_W + (size_t)gw * HC;
                const float* hv = g_dh[t & 1];
                float acc = 0.f;
                #pragma unroll 4
                for (int k = lane; k < HC; k += 32) {
                    float hk = (k < H2) ? hv[k] : g_ctx[k - H2];
                    acc += ww[k] * hk;
                }
                #pragma unroll
                for (int o = 16; o; o >>= 1) acc += __shfl_down_sync(0xffffffffu, acc, o);
                if (lane == 0) g_z[gw] = acc + W_b[gw];
            }
        }
        gbar(nb);

        // Phase L: logits = z @ lin_W^T + lin_b  (206 MB streamed, HBM-bound)
        {
            for (int i = tid; i < HC; i += NT) s_a[i] = g_z[i];
            __syncthreads();
            const float4* z4 = (const float4*)s_a;
            const int r0 = cta * ROWS_PER_CTA;
            const int r1 = min(VOCAB, r0 + ROWS_PER_CTA);
            float bv = -INFINITY; int bi = 0;
            float* olog = out_logits + (size_t)t * VOCAB;
            int r = r0 + warp;
            for (; r + 8 < r1; r += 16) {                 // 2-row unroll for MLP
                const float4* w0 = (const float4*)(lin_W + (size_t)r * HC);
                const float4* w1 = (const float4*)(lin_W + (size_t)(r + 8) * HC);
                float a0 = 0.f, a1 = 0.f;
                #pragma unroll
                for (int i = 0; i < 8; i++) {
                    float4 zz = z4[lane + 32 * i];
                    float4 x0 = w0[lane + 32 * i];
                    float4 x1 = w1[lane + 32 * i];
                    a0 += x0.x*zz.x + x0.y*zz.y + x0.z*zz.z + x0.w*zz.w;
                    a1 += x1.x*zz.x + x1.y*zz.y + x1.z*zz.z + x1.w*zz.w;
                }
                #pragma unroll
                for (int o = 16; o; o >>= 1) {
                    a0 += __shfl_down_sync(0xffffffffu, a0, o);
                    a1 += __shfl_down_sync(0xffffffffu, a1, o);
                }
                if (lane == 0) {
                    float v0 = a0 + lin_b[r];     olog[r]     = v0;
                    float v1 = a1 + lin_b[r + 8]; olog[r + 8] = v1;
                    if (v0 > bv || (v0 == bv && r     < bi)) { bv = v0; bi = r;     }
                    if (v1 > bv || (v1 == bv && r + 8 < bi)) { bv = v1; bi = r + 8; }
                }
            }
            for (; r < r1; r += 8) {
                const float4* w0 = (const float4*)(lin_W + (size_t)r * HC);
                float a0 = 0.f;
                #pragma unroll
                for (int i = 0; i < 8; i++) {
                    float4 zz = z4[lane + 32 * i];
                    float4 x0 = w0[lane + 32 * i];
                    a0 += x0.x*zz.x + x0.y*zz.y + x0.z*zz.z + x0.w*zz.w;
                }
                #pragma unroll
                for (int o = 16; o; o >>= 1) a0 += __shfl_down_sync(0xffffffffu, a0, o);
                if (lane == 0) {
                    float v0 = a0 + lin_b[r]; olog[r] = v0;
                    if (v0 > bv || (v0 == bv && r < bi)) { bv = v0; bi = r; }
                }
            }
            __syncthreads();
            if (lane == 0) { s_red[warp] = bv; s_redi[warp] = bi; }
            __syncthreads();
            if (tid == 0) {
                float v = s_red[0]; int ii = s_redi[0];
                for (int i = 1; i < 8; i++)
                    if (s_red[i] > v || (s_red[i] == v && s_redi[i] < ii)) { v = s_red[i]; ii = s_redi[i]; }
                g_pval[cta] = v; g_pidx[cta] = ii;
            }
        }
        gbar(nb);

        // Phase R: redundant global argmax reduce -> next word (no barrier needed)
        if (tid == 0) {
            float v = g_pval[0]; int ii = g_pidx[0];
            for (int i = 1; i < GRID; i++) {
                float pv = g_pval[i];
                if (pv > v) { v = pv; ii = g_pidx[i]; }
            }
            s_word = ii;
            if (cta == 0 && sent_off) out[1 + t] = (float)ii;
        }
        __syncthreads();
    }
}

extern "C" void kernel_launch(void* const* d_in, const int* in_sizes, int n_in,
                              void* d_out, int out_size)
{
    const int*   tokens  = (const int*)  d_in[0];
    // d_in[1] = trg_seqs (unused by forward)
    const float* enc_emb = (const float*)d_in[2];
    const float* dec_emb = (const float*)d_in[3];
    const float* eWi_f   = (const float*)d_in[4];
    const float* eWh_f   = (const float*)d_in[5];
    const float* eb_f    = (const float*)d_in[6];
    const float* eWi_b   = (const float*)d_in[7];
    const float* eWh_b   = (const float*)d_in[8];
    const float* eb_b    = (const float*)d_in[9];
    const float* dWi     = (const float*)d_in[10];
    const float* dWh     = (const float*)d_in[11];
    const float* db      = (const float*)d_in[12];
    const float* attn_W  = (const float*)d_in[13];
    const float* attn_b  = (const float*)d_in[14];
    const float* W_W     = (const float*)d_in[15];
    const float* W_b     = (const float*)d_in[16];
    const float* lin_W   = (const float*)d_in[17];
    const float* lin_b   = (const float*)d_in[18];

    // sentence (S+1 as float) + logits (S*V), or logits-only fallback
    long long need_full = (long long)(S + 1) + (long long)S * VOCAB;
    int sent_off = ((long long)out_size >= need_full) ? 1 : 0;

    init_kernel<<<1, 1>>>();
    seq2seq_kernel<<<GRID, NT>>>(tokens, enc_emb, dec_emb,
                                 eWi_f, eWh_f, eb_f, eWi_b, eWh_b, eb_b,
                                 dWi, dWh, db, attn_W, attn_b, W_W, W_b,
                                 lin_W, lin_b, (float*)d_out, sent_off);
}

// round 3
// speedup vs baseline: 1.1430x; 1.1403x over previous
#include <cuda_runtime.h>
#include <math.h>

#define S     512
#define E     256
#define H2    512
#define HC    1024
#define VOCAB 50257
#define GRID  148
#define NT    256
#define CBLK  340            // vocab cols per CTA block
#define CPAD  352            // padded (11 * 32)
#define RES_BLKS 72          // blocks kept L2-resident (default cache policy)

// ---------------- device scratch (static globals; no allocation) ----------------
__device__ float g_linT[(size_t)GRID * 1024 * CPAD];   // blocked transposed lin_W (~213MB)
__device__ float g_emb[S*E];
__device__ int   g_mask[S];
__device__ float g_ehf[2][E];
__device__ float g_ehb[2][E];
__device__ float g_outf[S*E];
__device__ float g_outb[S*E];
__device__ float g_encT[H2*S];     // [k][s], masked encoder outputs (transposed)
__device__ float g_A[S*H2];        // enc_masked @ attn_W
__device__ float g_dvec[S];        // enc_masked @ attn_b
__device__ float g_enchid[H2];
__device__ float g_dh[2][H2];      // decoder h, double buffered
__device__ float g_scores[S];
__device__ float g_ctx[H2];
__device__ float g_z[HC];
__device__ float g_pval[GRID];
__device__ int   g_pidx[GRID];
__device__ unsigned g_arrive;
__device__ unsigned g_epoch;
__device__ unsigned g_arr2[2];     // per-direction encoder barriers
__device__ unsigned g_ep2[2];

__global__ void init_kernel() {
    g_arrive = 0u; g_epoch = 0u;
    g_arr2[0] = 0u; g_arr2[1] = 0u; g_ep2[0] = 0u; g_ep2[1] = 0u;
}

// ---------------- lin_W transpose into blocked layout ----------------
__global__ void transpose_kernel(const float* __restrict__ lin_W) {
    __shared__ float tile[32][33];
    const int b  = blockIdx.x;          // 0..147
    const int kt = blockIdx.y * 32;     // k tile base
    const int x  = threadIdx.x & 31, y = threadIdx.x >> 5;   // y: 0..7
    for (int ct = 0; ct < CPAD; ct += 32) {
        #pragma unroll
        for (int yy = 0; yy < 4; yy++) {
            int c   = ct + y + 8 * yy;
            int row = b * CBLK + c;
            float v = 0.f;
            if (c < CBLK && row < VOCAB) v = lin_W[(size_t)row * HC + kt + x];
            tile[y + 8 * yy][x] = v;
        }
        __syncthreads();
        #pragma unroll
        for (int yy = 0; yy < 4; yy++) {
            int k = kt + y + 8 * yy;
            g_linT[(size_t)b * (1024 * CPAD) + (size_t)k * CPAD + ct + x] = tile[x][y + 8 * yy];
        }
        __syncthreads();
    }
}

__device__ __forceinline__ float sigf(float x) { return 1.f / (1.f + expf(-x)); }

__device__ __forceinline__ void gbar_gen(unsigned* arr, unsigned* ep, unsigned n, unsigned &nb) {
    __syncthreads();
    nb++;
    if (threadIdx.x == 0) {
        __threadfence();
        unsigned t = atomicAdd(arr, 1u);
        if (t == n - 1u) {
            *arr = 0u;
            __threadfence();
            atomicAdd(ep, 1u);
        } else {
            unsigned e;
            do {
                asm volatile("ld.acquire.gpu.u32 %0, [%1];" : "=r"(e) : "l"(ep));
            } while (e < nb);
        }
    }
    __syncthreads();
}
__device__ __forceinline__ void gbar(unsigned &nb) { gbar_gen(&g_arrive, &g_epoch, GRID, nb); }

__global__ void __launch_bounds__(NT, 1) seq2seq_kernel(
    const int*   __restrict__ tokens,
    const float* __restrict__ enc_emb,
    const float* __restrict__ dec_emb,
    const float* __restrict__ eWi_f, const float* __restrict__ eWh_f, const float* __restrict__ eb_f,
    const float* __restrict__ eWi_b, const float* __restrict__ eWh_b, const float* __restrict__ eb_b,
    const float* __restrict__ dWi,   const float* __restrict__ dWh,   const float* __restrict__ db,
    const float* __restrict__ attn_W, const float* __restrict__ attn_b,
    const float* __restrict__ W_W,    const float* __restrict__ W_b,
    const float* __restrict__ lin_W,  const float* __restrict__ lin_b,
    float* __restrict__ out, int sent_off)
{
    __shared__ float s_a[HC];            // 4KB
    __shared__ float s_b[H2];            // 2KB
    __shared__ float s_part[8 * CPAD];   // 11.3KB
    __shared__ float s_rv[NT];
    __shared__ int   s_ri[NT];
    __shared__ float s_red[32];
    __shared__ float s_ec[4];
    __shared__ float s_dc[4];
    __shared__ int   s_word;

    const int cta = blockIdx.x, tid = threadIdx.x;
    const int warp = tid >> 5, lane = tid & 31;
    unsigned nb = 0;
    float* out_logits = out + (sent_off ? (S + 1) : 0);

    // ---------- setup: embeddings, mask, zero initial LSTM states ----------
    for (int idx = cta * NT + tid; idx < S * E; idx += GRID * NT) {
        int t = idx / E, k = idx - t * E;
        g_emb[idx] = fmaxf(__ldg(enc_emb + (size_t)tokens[t] * E + k), 0.f);
    }
    for (int idx = cta * NT + tid; idx < S; idx += GRID * NT) g_mask[idx] = tokens[idx] > 0;
    for (int idx = cta * NT + tid; idx < E; idx += GRID * NT) { g_ehf[1][idx] = 0.f; g_ehb[1][idx] = 0.f; }
    if (tid < 4) { s_ec[tid] = 0.f; s_dc[tid] = 0.f; }
    gbar(nb);

    // ---------- encoder BiLSTM: CTAs 0..63 fwd, 64..127 bwd, own barriers ----------
    if (cta < 128) {
        const int dir   = cta >> 6;
        const int ubase = (cta & 63) * 4;
        const float* Wi = dir ? eWi_b : eWi_f;
        const float* Wh = dir ? eWh_b : eWh_f;
        const float* bb = dir ? eb_b  : eb_f;
        const int rl = tid >> 4, l16 = tid & 15;
        const int u = rl >> 2, gg = rl & 3;
        const int unit = ubase + u;
        const int row  = gg * E + unit;
        const float4* wi4 = (const float4*)(Wi + (size_t)row * E);
        const float4* wh4 = (const float4*)(Wh + (size_t)row * E);
        const float brow = __ldg(bb + row);
        unsigned nbe = 0;
        for (int t = 0; t < S; t++) {
            const int xt = dir ? (S - 1 - t) : t;
            const float* hrd = dir ? g_ehb[(t ^ 1) & 1] : g_ehf[(t ^ 1) & 1];
            for (int i = tid; i < E; i += NT) { s_a[i] = g_emb[xt * E + i]; s_b[i] = hrd[i]; }
            __syncthreads();
            const float4* a4 = (const float4*)s_a;
            const float4* b4 = (const float4*)s_b;
            float acc = 0.f;
            #pragma unroll
            for (int i = 0; i < 4; i++) {
                float4 w = __ldg(wi4 + l16 + 16 * i); float4 v = a4[l16 + 16 * i];
                acc += w.x*v.x + w.y*v.y + w.z*v.z + w.w*v.w;
            }
            #pragma unroll
            for (int i = 0; i < 4; i++) {
                float4 w = __ldg(wh4 + l16 + 16 * i); float4 v = b4[l16 + 16 * i];
                acc += w.x*v.x + w.y*v.y + w.z*v.z + w.w*v.w;
            }
            #pragma unroll
            for (int o = 8; o; o >>= 1) acc += __shfl_down_sync(0xffffffffu, acc, o, 16);
            if (l16 == 0) s_red[rl] = acc + brow;
            __syncthreads();
            if (tid < 4) {
                float gi = s_red[tid*4+0], gf = s_red[tid*4+1], gc = s_red[tid*4+2], go = s_red[tid*4+3];
                float c = sigf(gf) * s_ec[tid] + sigf(gi) * tanhf(gc);
                float h = sigf(go) * tanhf(c);
                s_ec[tid] = c;
                int uj = ubase + tid;
                (dir ? g_ehb[t & 1] : g_ehf[t & 1])[uj] = h;
                (dir ? g_outb : g_outf)[xt * E + uj]   = h;
            }
            gbar_gen(&g_arr2[dir], &g_ep2[dir], 64u, nbe);
        }
    }
    gbar(nb);   // CTAs 128..147 skip straight here

    // ---------- setup2: encT, A = enc_m @ attn_W, d = enc_m @ attn_b, enc_hidden ----------
    for (int idx = cta * NT + tid; idx < H2 * S; idx += GRID * NT) {
        int k = idx / S, s = idx - k * S;
        float v = (k < E) ? g_outf[s * E + k] : g_outb[s * E + (k - E)];
        g_encT[idx] = g_mask[s] ? v : 0.f;
    }
    for (int s = cta; s < S; s += GRID) {
        float m = g_mask[s] ? 1.f : 0.f;
        for (int j = tid; j < H2; j += NT)
            s_a[j] = ((j < E) ? g_outf[s * E + j] : g_outb[s * E + j - E]) * m;
        __syncthreads();
        for (int k = tid; k < H2; k += NT) {
            float acc = 0.f;
            #pragma unroll 4
            for (int j = 0; j < H2; j++) acc += s_a[j] * __ldg(attn_W + j * H2 + k);
            g_A[s * H2 + k] = acc;
        }
        if (tid == 0) {
            float acc = 0.f;
            for (int j = 0; j < H2; j++) acc += s_a[j] * __ldg(attn_b + j);
            g_dvec[s] = acc;
        }
        __syncthreads();
    }
    if (cta == 0) {
        for (int j = tid; j < E; j += NT) {
            float hf = g_outf[(S - 1) * E + j];
            float hb = g_outb[0 * E + j];
            g_enchid[j]     = hf; g_enchid[E + j] = hb;
            g_dh[1][j]      = hf; g_dh[1][E + j]  = hb;
        }
        if (tid == 0 && sent_off) out[0] = 1.0f;   // SOS
    }
    if (tid == 0) s_word = 1;                       // SOS
    gbar(nb);

    // ---------- autoregressive decode, 512 steps ----------
    for (int t = 0; t < S; t++) {
        // Phase G: decoder LSTM gates -> h, c (CTAs 0..127, 4 units each)
        if (cta < 128) {
            const int w = s_word;
            for (int i = tid; i < H2; i += NT) {
                s_a[i]      = fmaxf(__ldg(dec_emb + (size_t)w * H2 + i), 0.f);
                s_a[H2 + i] = g_enchid[i];
                s_b[i]      = g_dh[(t ^ 1) & 1][i];
            }
            __syncthreads();
            const int rl = tid >> 4, l16 = tid & 15;
            const int u = rl >> 2, gg = rl & 3;
            const int unit = (cta << 2) + u;
            const int row  = gg * H2 + unit;
            const float4* wi4 = (const float4*)(dWi + (size_t)row * HC);
            const float4* wh4 = (const float4*)(dWh + (size_t)row * H2);
            const float4* a4 = (const float4*)s_a;
            const float4* b4 = (const float4*)s_b;
            float acc = 0.f;
            #pragma unroll
            for (int i = 0; i < 16; i++) {
                float4 wv = __ldg(wi4 + l16 + 16 * i); float4 av = a4[l16 + 16 * i];
                acc += wv.x*av.x + wv.y*av.y + wv.z*av.z + wv.w*av.w;
            }
            #pragma unroll
            for (int i = 0; i < 8; i++) {
                float4 wv = __ldg(wh4 + l16 + 16 * i); float4 bv = b4[l16 + 16 * i];
                acc += wv.x*bv.x + wv.y*bv.y + wv.z*bv.z + wv.w*bv.w;
            }
            #pragma unroll
            for (int o = 8; o; o >>= 1) acc += __shfl_down_sync(0xffffffffu, acc, o, 16);
            if (l16 == 0) s_red[rl] = acc + __ldg(db + row);
            __syncthreads();
            if (tid < 4) {
                float gi = s_red[tid*4+0], gf = s_red[tid*4+1], gc = s_red[tid*4+2], go = s_red[tid*4+3];
                float c = sigf(gf) * s_dc[tid] + sigf(gi) * tanhf(gc);
                float h = sigf(go) * tanhf(c);
                s_dc[tid] = c;
                g_dh[t & 1][(cta << 2) + tid] = h;
            }
        }
        gbar(nb);

        // Phase S: scores = A @ h + d  (warps of CTAs 0..63)
        {
            const int gw = cta * 8 + warp;
            if (gw < S) {
                const float4* Ar4 = (const float4*)(g_A + (size_t)gw * H2);
                const float4* hv4 = (const float4*)(g_dh[t & 1]);
                float acc = 0.f;
                #pragma unroll
                for (int i = 0; i < 4; i++) {
                    float4 a = __ldg(Ar4 + lane + 32 * i);
                    float4 h = hv4[lane + 32 * i];
                    acc += a.x*h.x + a.y*h.y + a.z*h.z + a.w*h.w;
                }
                #pragma unroll
                for (int o = 16; o; o >>= 1) acc += __shfl_down_sync(0xffffffffu, acc, o);
                if (lane == 0) {
                    float sc = acc + g_dvec[gw];
                    g_scores[gw] = g_mask[gw] ? sc : -INFINITY;
                }
            }
        }
        gbar(nb);

        // Phase C: per-CTA redundant softmax + context (CTAs 0..63)
        if (cta < 64) {
            for (int i = tid; i < S; i += NT) s_b[i] = g_scores[i];
            __syncthreads();
            float m = -INFINITY;
            for (int i = tid; i < S; i += NT) m = fmaxf(m, s_b[i]);
            #pragma unroll
            for (int o = 16; o; o >>= 1) m = fmaxf(m, __shfl_down_sync(0xffffffffu, m, o));
            if (lane == 0) s_red[warp] = m;
            __syncthreads();
            if (tid == 0) {
                float mm = s_red[0];
                for (int i = 1; i < 8; i++) mm = fmaxf(mm, s_red[i]);
                s_red[16] = mm;
            }
            __syncthreads();
            const float mx = s_red[16];
            float sum = 0.f;
            for (int i = tid; i < S; i += NT) {
                float e = (mx == -INFINITY) ? 0.f : expf(s_b[i] - mx);
                s_b[i] = e; sum += e;
            }
            #pragma unroll
            for (int o = 16; o; o >>= 1) sum += __shfl_down_sync(0xffffffffu, sum, o);
            if (lane == 0) s_red[warp] = sum;
            __syncthreads();
            if (tid == 0) {
                float ss = 0.f;
                for (int i = 0; i < 8; i++) ss += s_red[i];
                s_red[17] = (ss > 0.f) ? 1.f / ss : 0.f;
            }
            __syncthreads();
            const float inv = s_red[17];
            for (int i = tid; i < S; i += NT) s_b[i] *= inv;
            __syncthreads();
            const int gw = cta * 8 + warp;                // 0..511
            const float4* et4 = (const float4*)(g_encT + (size_t)gw * S);
            const float4* w4  = (const float4*)s_b;
            float acc = 0.f;
            #pragma unroll
            for (int i = 0; i < 4; i++) {
                float4 e = __ldg(et4 + lane + 32 * i);
                float4 w = w4[lane + 32 * i];
                acc += e.x*w.x + e.y*w.y + e.z*w.z + e.w*w.w;
            }
            #pragma unroll
            for (int o = 16; o; o >>= 1) acc += __shfl_down_sync(0xffffffffu, acc, o);
            if (lane == 0) g_ctx[gw] = acc;
        }
        gbar(nb);

        // Phase Z: z = [h, ctx] @ W_W^T + W_b  (warps of CTAs 0..127)
        if (cta < 128) {
            for (int i = tid; i < H2; i += NT) {
                s_a[i]      = g_dh[t & 1][i];
                s_a[H2 + i] = g_ctx[i];
            }
            __syncthreads();
            const int gw = cta * 8 + warp;            // 0..1023
            const float4* ww4 = (const float4*)(W_W + (size_t)gw * HC);
            const float4* a4  = (const float4*)s_a;
            float acc = 0.f;
            #pragma unroll
            for (int i = 0; i < 8; i++) {
                float4 w = __ldg(ww4 + lane + 32 * i);
                float4 v = a4[lane + 32 * i];
                acc += w.x*v.x + w.y*v.y + w.z*v.z + w.w*v.w;
            }
            #pragma unroll
            for (int o = 16; o; o >>= 1) acc += __shfl_down_sync(0xffffffffu, acc, o);
            if (lane == 0) g_z[gw] = acc + __ldg(W_b + gw);
        }
        gbar(nb);

        // Phase L: logits = z @ lin_W^T + lin_b via blocked-transposed g_linT.
        // Each warp owns k-range [warp*128, warp*128+128), each lane 11 columns.
        {
            for (int i = tid; i < HC; i += NT) s_a[i] = g_z[i];
            __syncthreads();
            const float* wb = g_linT + (size_t)cta * (1024 * CPAD) + (size_t)warp * 128 * CPAD;
            const float* zw = s_a + warp * 128;
            float acc[11];
            #pragma unroll
            for (int j = 0; j < 11; j++) acc[j] = 0.f;
            if (cta < RES_BLKS) {
                #pragma unroll 2
                for (int k = 0; k < 128; k++) {
                    float zk = zw[k];
                    const float* row = wb + k * CPAD + lane;
                    #pragma unroll
                    for (int j = 0; j < 11; j++) acc[j] += zk * __ldg(row + 32 * j);
                }
            } else {
                #pragma unroll 2
                for (int k = 0; k < 128; k++) {
                    float zk = zw[k];
                    const float* row = wb + k * CPAD + lane;
                    #pragma unroll
                    for (int j = 0; j < 11; j++) acc[j] += zk * __ldcs(row + 32 * j);
                }
            }
            #pragma unroll
            for (int j = 0; j < 11; j++) s_part[warp * CPAD + lane + 32 * j] = acc[j];
            __syncthreads();
            const int base = cta * CBLK;
            const int ncol = min(CBLK, VOCAB - base);
            float bv = -INFINITY; int bi = 0x7fffffff;
            float* olog = out_logits + (size_t)t * VOCAB;
            #pragma unroll
            for (int cc = 0; cc < 2; cc++) {
                int c = tid + cc * NT;
                if (c < ncol) {
                    float sum = 0.f;
                    #pragma unroll
                    for (int w = 0; w < 8; w++) sum += s_part[w * CPAD + c];
                    float v = sum + __ldg(lin_b + base + c);
                    __stcs(olog + base + c, v);
                    if (v > bv) { bv = v; bi = base + c; }   // ascending c: > keeps lowest idx
                }
            }
            s_rv[tid] = bv; s_ri[tid] = bi;
            __syncthreads();
            for (int s2 = NT / 2; s2 > 0; s2 >>= 1) {
                if (tid < s2) {
                    float v2 = s_rv[tid + s2]; int i2 = s_ri[tid + s2];
                    if (v2 > s_rv[tid] || (v2 == s_rv[tid] && i2 < s_ri[tid])) {
                        s_rv[tid] = v2; s_ri[tid] = i2;
                    }
                }
                __syncthreads();
            }
            if (tid == 0) { g_pval[cta] = s_rv[0]; g_pidx[cta] = s_ri[0]; }
        }
        gbar(nb);

        // Phase R: redundant global argmax reduce -> next word (no barrier needed)
        if (tid == 0) {
            float v = g_pval[0]; int ii = g_pidx[0];
            for (int i = 1; i < GRID; i++) {
                float pv = g_pval[i];
                if (pv > v) { v = pv; ii = g_pidx[i]; }
            }
            s_word = ii;
            if (cta == 0 && sent_off) out[1 + t] = (float)ii;
        }
        __syncthreads();
    }
}

extern "C" void kernel_launch(void* const* d_in, const int* in_sizes, int n_in,
                              void* d_out, int out_size)
{
    const int*   tokens  = (const int*)  d_in[0];
    // d_in[1] = trg_seqs (unused by forward)
    const float* enc_emb = (const float*)d_in[2];
    const float* dec_emb = (const float*)d_in[3];
    const float* eWi_f   = (const float*)d_in[4];
    const float* eWh_f   = (const float*)d_in[5];
    const float* eb_f    = (const float*)d_in[6];
    const float* eWi_b   = (const float*)d_in[7];
    const float* eWh_b   = (const float*)d_in[8];
    const float* eb_b    = (const float*)d_in[9];
    const float* dWi     = (const float*)d_in[10];
    const float* dWh     = (const float*)d_in[11];
    const float* db      = (const float*)d_in[12];
    const float* attn_W  = (const float*)d_in[13];
    const float* attn_b  = (const float*)d_in[14];
    const float* W_W     = (const float*)d_in[15];
    const float* W_b     = (const float*)d_in[16];
    const float* lin_W   = (const float*)d_in[17];
    const float* lin_b   = (const float*)d_in[18];

    long long need_full = (long long)(S + 1) + (long long)S * VOCAB;
    int sent_off = ((long long)out_size >= need_full) ? 1 : 0;

    init_kernel<<<1, 1>>>();
    transpose_kernel<<<dim3(GRID, 32), 256>>>(lin_W);
    seq2seq_kernel<<<GRID, NT>>>(tokens, enc_emb, dec_emb,
                                 eWi_f, eWh_f, eb_f, eWi_b, eWh_b, eb_b,
                                 dWi, dWh, db, attn_W, attn_b, W_W, W_b,
                                 lin_W, lin_b, (float*)d_out, sent_off);
}

// round 5
// speedup vs baseline: 1.3627x; 1.1923x over previous
#include <cuda_runtime.h>
#include <math.h>

#define S     512
#define E     256
#define H2    512
#define HC    1024
#define VOCAB 50257
#define GRID  148
#define NT    512
#define CBLK  340            // vocab cols per CTA block
#define CPAD  352            // padded (88 float4)
#define RES_BLKS 64          // blocks kept L2-resident (default cache policy)

// ---------------- device scratch (static globals; no allocation) ----------------
__device__ float g_linT[(size_t)GRID * 1024 * CPAD];   // blocked transposed lin_W (~213MB)
__device__ float g_emb[S*E];
__device__ int   g_mask[S];
__device__ float g_ehf[2][E];
__device__ float g_ehb[2][E];
__device__ float g_outf[S*E];
__device__ float g_outb[S*E];
__device__ float g_encT[H2*S];
__device__ float g_A[S*H2];
__device__ float g_dvec[S];
__device__ float g_enchid[H2];
__device__ float g_dh[2][H2];
__device__ float g_scores[S];
__device__ float g_ctx[H2];
__device__ float g_z[HC];
__device__ float g_pval[GRID];
__device__ int   g_pidx[GRID];
__device__ unsigned g_flags[GRID * 8];   // per-CTA arrival flags (32B apart)
__device__ unsigned g_epoch;
__device__ unsigned g_arr2[2];           // per-direction encoder barriers
__device__ unsigned g_ep2[2];

__global__ void init_kernel() {
    int i = threadIdx.x;
    if (i == 0) { g_epoch = 0u; g_arr2[0] = 0u; g_arr2[1] = 0u; g_ep2[0] = 0u; g_ep2[1] = 0u; }
    for (int j = i; j < GRID * 8; j += blockDim.x) g_flags[j] = 0u;
}

// ---------------- lin_W transpose into blocked layout ----------------
__global__ void transpose_kernel(const float* __restrict__ lin_W) {
    __shared__ float tile[32][33];
    const int b  = blockIdx.x;          // 0..147
    const int kt = blockIdx.y * 32;     // k tile base
    const int x  = threadIdx.x & 31, y = threadIdx.x >> 5;   // y: 0..7
    for (int ct = 0; ct < CPAD; ct += 32) {
        #pragma unroll
        for (int yy = 0; yy < 4; yy++) {
            int c   = ct + y + 8 * yy;
            int row = b * CBLK + c;
            float v = 0.f;
            if (c < CBLK && row < VOCAB) v = lin_W[(size_t)row * HC + kt + x];
            tile[y + 8 * yy][x] = v;
        }
        __syncthreads();
        #pragma unroll
        for (int yy = 0; yy < 4; yy++) {
            int k = kt + y + 8 * yy;
            g_linT[(size_t)b * (1024 * CPAD) + (size_t)k * CPAD + ct + x] = tile[x][y + 8 * yy];
        }
        __syncthreads();
    }
}

__device__ __forceinline__ float sigf(float x) { return 1.f / (1.f + expf(-x)); }

// encoder sub-barrier (64 CTAs): atomic-based, low contention
__device__ __forceinline__ void gbar_enc(unsigned* arr, unsigned* ep, unsigned &nb) {
    __syncthreads();
    nb++;
    if (threadIdx.x == 0) {
        __threadfence();
        unsigned t = atomicAdd(arr, 1u);
        if (t == 63u) {
            *arr = 0u;
            __threadfence();
            atomicAdd(ep, 1u);
        } else {
            unsigned e;
            do { asm volatile("ld.acquire.gpu.u32 %0, [%1];" : "=r"(e) : "l"(ep)); } while (e < nb);
        }
    }
    __syncthreads();
}

// main grid barrier: per-CTA flag store, CTA0 warp scans, epoch release
__device__ __forceinline__ void gbar(int cta, unsigned &nb) {
    __syncthreads();
    nb++;
    if (threadIdx.x < 32) {
        const int lane = threadIdx.x;
        if (lane == 0)
            asm volatile("st.release.gpu.u32 [%0], %1;" :: "l"(&g_flags[cta * 8]), "r"(nb) : "memory");
        if (cta == 0) {
            bool done = false;
            while (!done) {
                bool ok = true;
                #pragma unroll
                for (int i = 0; i < 5; i++) {
                    int idx = lane + 32 * i;
                    if (idx < GRID) {
                        unsigned v;
                        asm volatile("ld.acquire.gpu.u32 %0, [%1];" : "=r"(v) : "l"(&g_flags[idx * 8]) : "memory");
                        if (v < nb) ok = false;
                    }
                }
                done = __all_sync(0xffffffffu, ok);
            }
            if (lane == 0)
                asm volatile("st.release.gpu.u32 [%0], %1;" :: "l"(&g_epoch), "r"(nb) : "memory");
        } else if (lane == 0) {
            unsigned e;
            do { asm volatile("ld.acquire.gpu.u32 %0, [%1];" : "=r"(e) : "l"(&g_epoch) : "memory"); } while (e < nb);
        }
    }
    __syncthreads();
}

__device__ __forceinline__ void fma4(float4& a, const float4& c, float s) {
    a.x = fmaf(s, c.x, a.x); a.y = fmaf(s, c.y, a.y);
    a.z = fmaf(s, c.z, a.z); a.w = fmaf(s, c.w, a.w);
}

template<int USE_CS>
__device__ __forceinline__ void linT_dot(const float* wb, const float* zw, int lane, bool third,
                                         float4& a0, float4& a1, float4& a2)
{
    const float4 zf = make_float4(0.f, 0.f, 0.f, 0.f);
    const float4* rp = (const float4*)wb;
    float4 c0, c1, c2;
    if (USE_CS) {
        c0 = __ldcs(rp + lane); c1 = __ldcs(rp + lane + 32);
        c2 = third ? __ldcs(rp + lane + 64) : zf;
    } else {
        c0 = __ldg(rp + lane);  c1 = __ldg(rp + lane + 32);
        c2 = third ? __ldg(rp + lane + 64) : zf;
    }
    #pragma unroll 4
    for (int k = 0; k < 63; k++) {
        const float4* np = (const float4*)(wb + (k + 1) * CPAD);
        float4 n0, n1, n2;
        if (USE_CS) {
            n0 = __ldcs(np + lane); n1 = __ldcs(np + lane + 32);
            n2 = third ? __ldcs(np + lane + 64) : zf;
        } else {
            n0 = __ldg(np + lane);  n1 = __ldg(np + lane + 32);
            n2 = third ? __ldg(np + lane + 64) : zf;
        }
        float zk = zw[k];
        fma4(a0, c0, zk); fma4(a1, c1, zk); fma4(a2, c2, zk);
        c0 = n0; c1 = n1; c2 = n2;
    }
    float zk = zw[63];
    fma4(a0, c0, zk); fma4(a1, c1, zk); fma4(a2, c2, zk);
}

__global__ void __launch_bounds__(NT, 1) seq2seq_kernel(
    const int*   __restrict__ tokens,
    const float* __restrict__ enc_emb,
    const float* __restrict__ dec_emb,
    const float* __restrict__ eWi_f, const float* __restrict__ eWh_f, const float* __restrict__ eb_f,
    const float* __restrict__ eWi_b, const float* __restrict__ eWh_b, const float* __restrict__ eb_b,
    const float* __restrict__ dWi,   const float* __restrict__ dWh,   const float* __restrict__ db,
    const float* __restrict__ attn_W, const float* __restrict__ attn_b,
    const float* __restrict__ W_W,    const float* __restrict__ W_b,
    const float* __restrict__ lin_W,  const float* __restrict__ lin_b,
    float* __restrict__ out, int sent_off)
{
    __shared__ float s_a[HC];            // 4KB
    __shared__ float s_b[H2];            // 2KB
    __shared__ float s_part[16 * CPAD];  // 22.5KB
    __shared__ float s_rv[16];
    __shared__ int   s_ri[16];
    __shared__ float s_red[32];
    __shared__ float s_ec[4];
    __shared__ float s_dc[4];
    __shared__ int   s_word;

    const int cta = blockIdx.x, tid = threadIdx.x;
    const int warp = tid >> 5, lane = tid & 31;
    unsigned nb = 0;
    float* out_logits = out + (sent_off ? (S + 1) : 0);

    // ---------- setup ----------
    for (int idx = cta * NT + tid; idx < S * E; idx += GRID * NT) {
        int t = idx / E, k = idx - t * E;
        g_emb[idx] = fmaxf(__ldg(enc_emb + (size_t)tokens[t] * E + k), 0.f);
    }
    for (int idx = cta * NT + tid; idx < S; idx += GRID * NT) g_mask[idx] = tokens[idx] > 0;
    for (int idx = cta * NT + tid; idx < E; idx += GRID * NT) { g_ehf[1][idx] = 0.f; g_ehb[1][idx] = 0.f; }
    if (tid < 4) { s_ec[tid] = 0.f; s_dc[tid] = 0.f; }
    gbar(cta, nb);

    // ---------- encoder BiLSTM: CTAs 0..63 fwd, 64..127 bwd ----------
    if (cta < 128) {
        const int dir   = cta >> 6;
        const int ubase = (cta & 63) * 4;
        const float* Wi = dir ? eWi_b : eWi_f;
        const float* Wh = dir ? eWh_b : eWh_f;
        const float* bb = dir ? eb_b  : eb_f;
        const int u = warp >> 2, gg = warp & 3;
        const int row = gg * E + (ubase + u);
        const float4* wi4 = (const float4*)(Wi + (size_t)row * E);
        const float4* wh4 = (const float4*)(Wh + (size_t)row * E);
        const float brow = __ldg(bb + row);
        unsigned nbe = 0;
        for (int t = 0; t < S; t++) {
            const int xt = dir ? (S - 1 - t) : t;
            const float* hrd = dir ? g_ehb[(t ^ 1) & 1] : g_ehf[(t ^ 1) & 1];
            if (tid < E) { s_a[tid] = g_emb[xt * E + tid]; s_b[tid] = hrd[tid]; }
            __syncthreads();
            const float4* a4 = (const float4*)s_a;
            const float4* b4 = (const float4*)s_b;
            float acc = 0.f;
            #pragma unroll
            for (int i = 0; i < 2; i++) {
                float4 w = __ldg(wi4 + lane + 32 * i); float4 v = a4[lane + 32 * i];
                acc += w.x*v.x + w.y*v.y + w.z*v.z + w.w*v.w;
                float4 w2 = __ldg(wh4 + lane + 32 * i); float4 v2 = b4[lane + 32 * i];
                acc += w2.x*v2.x + w2.y*v2.y + w2.z*v2.z + w2.w*v2.w;
            }
            #pragma unroll
            for (int o = 16; o; o >>= 1) acc += __shfl_down_sync(0xffffffffu, acc, o);
            if (lane == 0) s_red[warp] = acc + brow;
            __syncthreads();
            if (tid < 4) {
                float gi = s_red[tid*4+0], gf = s_red[tid*4+1], gc = s_red[tid*4+2], go = s_red[tid*4+3];
                float c = sigf(gf) * s_ec[tid] + sigf(gi) * tanhf(gc);
                float h = sigf(go) * tanhf(c);
                s_ec[tid] = c;
                int uj = ubase + tid;
                (dir ? g_ehb[t & 1] : g_ehf[t & 1])[uj] = h;
                (dir ? g_outb : g_outf)[xt * E + uj]   = h;
            }
            gbar_enc(&g_arr2[dir], &g_ep2[dir], nbe);
        }
    }
    gbar(cta, nb);

    // ---------- setup2: encT, A, dvec, enc_hidden ----------
    for (int idx = cta * NT + tid; idx < H2 * S; idx += GRID * NT) {
        int k = idx / S, s = idx - k * S;
        float v = (k < E) ? g_outf[s * E + k] : g_outb[s * E + (k - E)];
        g_encT[idx] = g_mask[s] ? v : 0.f;
    }
    for (int s = cta; s < S; s += GRID) {
        float m = g_mask[s] ? 1.f : 0.f;
        for (int j = tid; j < H2; j += NT)
            s_b[j] = ((j < E) ? g_outf[s * E + j] : g_outb[s * E + j - E]) * m;
        __syncthreads();
        if (tid < H2) {
            const int k = tid;
            float acc = 0.f;
            #pragma unroll 4
            for (int j = 0; j < H2; j++) acc += s_b[j] * __ldg(attn_W + j * H2 + k);
            g_A[s * H2 + k] = acc;
        }
        if (tid == 0) {
            float acc = 0.f;
            for (int j = 0; j < H2; j++) acc += s_b[j] * __ldg(attn_b + j);
            g_dvec[s] = acc;
        }
        __syncthreads();
    }
    if (cta == 0) {
        for (int j = tid; j < E; j += NT) {
            float hf = g_outf[(S - 1) * E + j];
            float hb = g_outb[0 * E + j];
            g_enchid[j]     = hf; g_enchid[E + j] = hb;
            g_dh[1][j]      = hf; g_dh[1][E + j]  = hb;
        }
        if (tid == 0 && sent_off) out[0] = 1.0f;   // SOS
    }
    if (tid == 0) s_word = 1;                       // SOS
    gbar(cta, nb);

    // ---------- autoregressive decode, 512 steps ----------
    for (int t = 0; t < S; t++) {
        // Phase G: decoder LSTM (CTAs 0..127, warp-per-row, 16 rows/CTA)
        if (cta < 128) {
            const int w = s_word;
            if (tid < H2) {
                s_a[tid]      = fmaxf(__ldg(dec_emb + (size_t)w * H2 + tid), 0.f);
                s_a[H2 + tid] = g_enchid[tid];
                s_b[tid]      = g_dh[(t ^ 1) & 1][tid];
            }
            __syncthreads();
            const int u = warp >> 2, gg = warp & 3;
            const int row = gg * H2 + (cta * 4 + u);
            const float4* wi4 = (const float4*)(dWi + (size_t)row * HC);
            const float4* wh4 = (const float4*)(dWh + (size_t)row * H2);
            const float4* a4 = (const float4*)s_a;
            const float4* b4 = (const float4*)s_b;
            float acc = 0.f;
            #pragma unroll
            for (int i = 0; i < 8; i++) {
                float4 wv = __ldg(wi4 + lane + 32 * i); float4 av = a4[lane + 32 * i];
                acc += wv.x*av.x + wv.y*av.y + wv.z*av.z + wv.w*av.w;
            }
            #pragma unroll
            for (int i = 0; i < 4; i++) {
                float4 wv = __ldg(wh4 + lane + 32 * i); float4 bv = b4[lane + 32 * i];
                acc += wv.x*bv.x + wv.y*bv.y + wv.z*bv.z + wv.w*bv.w;
            }
            #pragma unroll
            for (int o = 16; o; o >>= 1) acc += __shfl_down_sync(0xffffffffu, acc, o);
            if (lane == 0) s_red[warp] = acc + __ldg(db + row);
            __syncthreads();
            if (tid < 4) {
                float gi = s_red[tid*4+0], gf = s_red[tid*4+1], gc = s_red[tid*4+2], go = s_red[tid*4+3];
                float c = sigf(gf) * s_dc[tid] + sigf(gi) * tanhf(gc);
                float h = sigf(go) * tanhf(c);
                s_dc[tid] = c;
                g_dh[t & 1][cta * 4 + tid] = h;
            }
        }
        gbar(cta, nb);

        // Phase S: scores = A @ h + d  (CTAs 0..31, warp-per-score)
        if (cta < 32) {
            const int gw = cta * 16 + warp;
            const float4* Ar4 = (const float4*)(g_A + (size_t)gw * H2);
            const float4* hv4 = (const float4*)(g_dh[t & 1]);
            float acc = 0.f;
            #pragma unroll
            for (int i = 0; i < 4; i++) {
                float4 a = __ldg(Ar4 + lane + 32 * i);
                float4 h = hv4[lane + 32 * i];
                acc += a.x*h.x + a.y*h.y + a.z*h.z + a.w*h.w;
            }
            #pragma unroll
            for (int o = 16; o; o >>= 1) acc += __shfl_down_sync(0xffffffffu, acc, o);
            if (lane == 0) {
                float sc = acc + g_dvec[gw];
                g_scores[gw] = g_mask[gw] ? sc : -INFINITY;
            }
        }
        gbar(cta, nb);

        // Phase C: redundant softmax + context (CTAs 0..31)
        if (cta < 32) {
            s_b[tid] = g_scores[tid];
            __syncthreads();
            float m = s_b[tid];
            #pragma unroll
            for (int o = 16; o; o >>= 1) m = fmaxf(m, __shfl_down_sync(0xffffffffu, m, o));
            if (lane == 0) s_red[warp] = m;
            __syncthreads();
            if (tid == 0) {
                float mm = s_red[0];
                #pragma unroll
                for (int i = 1; i < 16; i++) mm = fmaxf(mm, s_red[i]);
                s_red[16] = mm;
            }
            __syncthreads();
            const float mx = s_red[16];
            float e = (mx == -INFINITY) ? 0.f : expf(s_b[tid] - mx);
            float sum = e;
            #pragma unroll
            for (int o = 16; o; o >>= 1) sum += __shfl_down_sync(0xffffffffu, sum, o);
            if (lane == 0) s_red[warp] = sum;
            __syncthreads();
            if (tid == 0) {
                float ss = 0.f;
                #pragma unroll
                for (int i = 0; i < 16; i++) ss += s_red[i];
                s_red[17] = (ss > 0.f) ? 1.f / ss : 0.f;
            }
            __syncthreads();
            s_b[tid] = e * s_red[17];
            __syncthreads();
            const int gw = cta * 16 + warp;               // 0..511
            const float4* et4 = (const float4*)(g_encT + (size_t)gw * S);
            const float4* w4  = (const float4*)s_b;
            float acc = 0.f;
            #pragma unroll
            for (int i = 0; i < 4; i++) {
                float4 ev = __ldg(et4 + lane + 32 * i);
                float4 wv = w4[lane + 32 * i];
                acc += ev.x*wv.x + ev.y*wv.y + ev.z*wv.z + ev.w*wv.w;
            }
            #pragma unroll
            for (int o = 16; o; o >>= 1) acc += __shfl_down_sync(0xffffffffu, acc, o);
            if (lane == 0) g_ctx[gw] = acc;
        }
        gbar(cta, nb);

        // Phase Z: z = [h, ctx] @ W_W^T + W_b  (CTAs 0..63, warp-per-row)
        if (cta < 64) {
            if (tid < H2) {
                s_a[tid]      = g_dh[t & 1][tid];
                s_a[H2 + tid] = g_ctx[tid];
            }
            __syncthreads();
            const int gw = cta * 16 + warp;               // 0..1023
            const float4* ww4 = (const float4*)(W_W + (size_t)gw * HC);
            const float4* a4  = (const float4*)s_a;
            float acc = 0.f;
            #pragma unroll
            for (int i = 0; i < 8; i++) {
                float4 w = __ldg(ww4 + lane + 32 * i);
                float4 v = a4[lane + 32 * i];
                acc += w.x*v.x + w.y*v.y + w.z*v.z + w.w*v.w;
            }
            #pragma unroll
            for (int o = 16; o; o >>= 1) acc += __shfl_down_sync(0xffffffffu, acc, o);
            if (lane == 0) g_z[gw] = acc + __ldg(W_b + gw);
        }
        gbar(cta, nb);

        // Phase L: logits via blocked-transposed g_linT (warp owns k-range of 64)
        {
            for (int i = tid; i < HC; i += NT) s_a[i] = g_z[i];
            __syncthreads();
            const float* wb = g_linT + (size_t)cta * (1024 * CPAD) + (size_t)(warp * 64) * CPAD;
            const float* zw = s_a + warp * 64;
            const bool third = lane < 24;
            float4 a0 = make_float4(0,0,0,0), a1 = a0, a2 = a0;
            if (cta < RES_BLKS) linT_dot<0>(wb, zw, lane, third, a0, a1, a2);
            else                linT_dot<1>(wb, zw, lane, third, a0, a1, a2);
            float4* sp = (float4*)(s_part + warp * CPAD);
            sp[lane] = a0; sp[lane + 32] = a1;
            if (third) sp[lane + 64] = a2;
            __syncthreads();
            const int base = cta * CBLK;
            const int ncol = min(CBLK, VOCAB - base);
            float bv = -INFINITY; int bi = 0x7fffffff;
            float* olog = out_logits + (size_t)t * VOCAB;
            if (tid < ncol) {
                float sum = 0.f;
                #pragma unroll
                for (int w = 0; w < 16; w++) sum += s_part[w * CPAD + tid];
                float v = sum + __ldg(lin_b + base + tid);
                __stcs(olog + base + tid, v);
                bv = v; bi = base + tid;
            }
            #pragma unroll
            for (int o = 16; o; o >>= 1) {
                float ov = __shfl_down_sync(0xffffffffu, bv, o);
                int   oi = __shfl_down_sync(0xffffffffu, bi, o);
                if (ov > bv || (ov == bv && oi < bi)) { bv = ov; bi = oi; }
            }
            if (lane == 0) { s_rv[warp] = bv; s_ri[warp] = bi; }
            __syncthreads();
            if (warp == 0) {
                float v = (lane < 16) ? s_rv[lane] : -INFINITY;
                int  ii = (lane < 16) ? s_ri[lane] : 0x7fffffff;
                #pragma unroll
                for (int o = 8; o; o >>= 1) {
                    float ov = __shfl_down_sync(0xffffffffu, v, o);
                    int   oi = __shfl_down_sync(0xffffffffu, ii, o);
                    if (ov > v || (ov == v && oi < ii)) { v = ov; ii = oi; }
                }
                if (lane == 0) { g_pval[cta] = v; g_pidx[cta] = ii; }
            }
        }
        gbar(cta, nb);

        // Phase R: warp-parallel global argmax -> next word
        if (warp == 0) {
            float v = -INFINITY; int ii = 0x7fffffff;
            #pragma unroll
            for (int i = 0; i < 5; i++) {
                int idx = lane + 32 * i;
                if (idx < GRID) {
                    float pv = g_pval[idx]; int pi = g_pidx[idx];
                    if (pv > v || (pv == v && pi < ii)) { v = pv; ii = pi; }
                }
            }
            #pragma unroll
            for (int o = 16; o; o >>= 1) {
                float ov = __shfl_down_sync(0xffffffffu, v, o);
                int   oi = __shfl_down_sync(0xffffffffu, ii, o);
                if (ov > v || (ov == v && oi < ii)) { v = ov; ii = oi; }
            }
            if (lane == 0) {
                s_word = ii;
                if (cta == 0 && sent_off) out[1 + t] = (float)ii;
            }
        }
        __syncthreads();
    }
}

extern "C" void kernel_launch(void* const* d_in, const int* in_sizes, int n_in,
                              void* d_out, int out_size)
{
    const int*   tokens  = (const int*)  d_in[0];
    const float* enc_emb = (const float*)d_in[2];
    const float* dec_emb = (const float*)d_in[3];
    const float* eWi_f   = (const float*)d_in[4];
    const float* eWh_f   = (const float*)d_in[5];
    const float* eb_f    = (const float*)d_in[6];
    const float* eWi_b   = (const float*)d_in[7];
    const float* eWh_b   = (const float*)d_in[8];
    const float* eb_b    = (const float*)d_in[9];
    const float* dWi     = (const float*)d_in[10];
    const float* dWh     = (const float*)d_in[11];
    const float* db      = (const float*)d_in[12];
    const float* attn_W  = (const float*)d_in[13];
    const float* attn_b  = (const float*)d_in[14];
    const float* W_W     = (const float*)d_in[15];
    const float* W_b     = (const float*)d_in[16];
    const float* lin_W   = (const float*)d_in[17];
    const float* lin_b   = (const float*)d_in[18];

    long long need_full = (long long)(S + 1) + (long long)S * VOCAB;
    int sent_off = ((long long)out_size >= need_full) ? 1 : 0;

    init_kernel<<<1, 256>>>();
    transpose_kernel<<<dim3(GRID, 32), 256>>>(lin_W);
    seq2seq_kernel<<<GRID, NT>>>(tokens, enc_emb, dec_emb,
                                 eWi_f, eWh_f, eb_f, eWi_b, eWh_b, eb_b,
                                 dWi, dWh, db, attn_W, attn_b, W_W, W_b,
                                 lin_W, lin_b, (float*)d_out, sent_off);
}

// round 6
// speedup vs baseline: 1.5619x; 1.1462x over previous
#include <cuda_runtime.h>
#include <math.h>

#define S     512
#define E     256
#define H2    512
#define HC    1024
#define VOCAB 50257
#define GRID  148
#define NT    512
#define CBLK  340            // vocab cols per CTA block
#define CPAD  352            // padded (88 float4)
#define RES_BLKS 64          // blocks kept L2-resident (default cache policy)

// ---------------- device scratch (static globals; no allocation) ----------------
__device__ float g_linT[(size_t)GRID * 1024 * CPAD];   // blocked transposed lin_W (~213MB)
__device__ float g_emb[S*E];
__device__ int   g_mask[S];
__device__ float g_ehf[2][E];
__device__ float g_ehb[2][E];
__device__ float g_outf[S*E];
__device__ float g_outb[S*E];
__device__ float g_encT[H2*S];
__device__ float g_A[S*H2];
__device__ float g_dvec[S];
__device__ float g_enchid[H2];
__device__ float g_dh[2][H2];
__device__ float g_scores[S];
__device__ float g_ctx[H2];
__device__ float g_z[HC];
__device__ float g_pval[GRID];
__device__ int   g_pidx[GRID];
// generation-counting barriers: monotonic, replay-safe (A = gen*N, R = gen at launch exit)
__device__ unsigned long long g_bA, g_bR;
__device__ unsigned long long g_eA[2], g_eR[2];

__device__ __forceinline__ float sigf(float x) { return 1.f / (1.f + expf(-x)); }

__device__ __forceinline__ void gbar_n(unsigned long long* A, unsigned long long* R, unsigned n) {
    __syncthreads();
    if (threadIdx.x == 0) {
        __threadfence();
        unsigned long long pos = atomicAdd(A, 1ULL);
        unsigned long long gen = pos / n;
        if (pos - gen * n == n - 1ULL) {
            __threadfence();
            atomicAdd(R, 1ULL);
        } else {
            unsigned long long r;
            do { asm volatile("ld.acquire.gpu.u64 %0, [%1];" : "=l"(r) : "l"(R) : "memory"); } while (r <= gen);
        }
    }
    __syncthreads();
}
__device__ __forceinline__ void gbar() { gbar_n(&g_bA, &g_bR, GRID); }

__device__ __forceinline__ void fma4(float4& a, const float4& c, float s) {
    a.x = fmaf(s, c.x, a.x); a.y = fmaf(s, c.y, a.y);
    a.z = fmaf(s, c.z, a.z); a.w = fmaf(s, c.w, a.w);
}

// Phase L inner GEMV over one warp's 64 k-rows, depth-2 software pipeline.
template<int USE_CS>
__device__ __forceinline__ void linT_dot(const float* wb, const float* zw, int lane, bool third,
                                         float4& a0, float4& a1, float4& a2)
{
    const float4 zf = make_float4(0.f, 0.f, 0.f, 0.f);
#define LDW(p) (USE_CS ? __ldcs(p) : __ldg(p))
    const float4* r0 = (const float4*)wb;
    const float4* r1 = (const float4*)(wb + CPAD);
    float4 b00 = LDW(r0 + lane), b01 = LDW(r0 + lane + 32), b02 = third ? LDW(r0 + lane + 64) : zf;
    float4 b10 = LDW(r1 + lane), b11 = LDW(r1 + lane + 32), b12 = third ? LDW(r1 + lane + 64) : zf;
    #pragma unroll 1
    for (int k = 0; k < 62; k += 2) {
        const float4* rn = (const float4*)(wb + (k + 2) * CPAD);
        float4 n00 = LDW(rn + lane), n01 = LDW(rn + lane + 32), n02 = third ? LDW(rn + lane + 64) : zf;
        float z0 = zw[k];
        fma4(a0, b00, z0); fma4(a1, b01, z0); fma4(a2, b02, z0);
        b00 = n00; b01 = n01; b02 = n02;
        const float4* rm = (const float4*)(wb + (k + 3) * CPAD);
        float4 n10 = LDW(rm + lane), n11 = LDW(rm + lane + 32), n12 = third ? LDW(rm + lane + 64) : zf;
        float z1 = zw[k + 1];
        fma4(a0, b10, z1); fma4(a1, b11, z1); fma4(a2, b12, z1);
        b10 = n10; b11 = n11; b12 = n12;
    }
    float z0 = zw[62];
    fma4(a0, b00, z0); fma4(a1, b01, z0); fma4(a2, b02, z0);
    float z1 = zw[63];
    fma4(a0, b10, z1); fma4(a1, b11, z1); fma4(a2, b12, z1);
#undef LDW
}

__global__ void __launch_bounds__(NT, 1) seq2seq_kernel(
    const int*   __restrict__ tokens,
    const float* __restrict__ enc_emb,
    const float* __restrict__ dec_emb,
    const float* __restrict__ eWi_f, const float* __restrict__ eWh_f, const float* __restrict__ eb_f,
    const float* __restrict__ eWi_b, const float* __restrict__ eWh_b, const float* __restrict__ eb_b,
    const float* __restrict__ dWi,   const float* __restrict__ dWh,   const float* __restrict__ db,
    const float* __restrict__ attn_W, const float* __restrict__ attn_b,
    const float* __restrict__ W_W,    const float* __restrict__ W_b,
    const float* __restrict__ lin_W,  const float* __restrict__ lin_b,
    float* __restrict__ out, int sent_off)
{
    __shared__ float s_a[HC];            // 4KB
    __shared__ float s_b[H2];            // 2KB
    __shared__ float s_part[16 * CPAD];  // 22.5KB (also reused as transpose tile)
    __shared__ float s_rv[16];
    __shared__ int   s_ri[16];
    __shared__ float s_red[32];
    __shared__ float s_ec[4];
    __shared__ float s_dc[4];
    __shared__ int   s_word;

    const int cta = blockIdx.x, tid = threadIdx.x;
    const int warp = tid >> 5, lane = tid & 31;
    float* out_logits = out + (sent_off ? (S + 1) : 0);

    // ---------- phase T: transpose own lin_W block into g_linT (pre-warms L2 slab) ----------
    {
        float (*tile)[33] = (float (*)[33])s_part;   // 32x33
        const int x = lane, y = warp;                // y: 0..15
        float* dst = g_linT + (size_t)cta * (1024 * CPAD);
        for (int kt = 0; kt < 1024; kt += 32) {
            for (int ct = 0; ct < CPAD; ct += 32) {
                #pragma unroll
                for (int yy = 0; yy < 2; yy++) {
                    int c   = ct + y + 16 * yy;
                    int row = cta * CBLK + c;
                    float v = 0.f;
                    if (c < CBLK && row < VOCAB) v = __ldg(lin_W + (size_t)row * HC + kt + x);
                    tile[y + 16 * yy][x] = v;
                }
                __syncthreads();
                #pragma unroll
                for (int yy = 0; yy < 2; yy++) {
                    int k = kt + y + 16 * yy;
                    dst[(size_t)k * CPAD + ct + x] = tile[x][y + 16 * yy];
                }
                __syncthreads();
            }
        }
    }

    // ---------- setup ----------
    for (int idx = cta * NT + tid; idx < S * E; idx += GRID * NT) {
        int t = idx / E, k = idx - t * E;
        g_emb[idx] = fmaxf(__ldg(enc_emb + (size_t)tokens[t] * E + k), 0.f);
    }
    for (int idx = cta * NT + tid; idx < S; idx += GRID * NT) g_mask[idx] = tokens[idx] > 0;
    for (int idx = cta * NT + tid; idx < E; idx += GRID * NT) { g_ehf[1][idx] = 0.f; g_ehb[1][idx] = 0.f; }
    if (tid < 4) { s_ec[tid] = 0.f; s_dc[tid] = 0.f; }
    gbar();

    // ---------- encoder BiLSTM: CTAs 0..63 fwd, 64..127 bwd ----------
    if (cta < 128) {
        const int dir   = cta >> 6;
        const int ubase = (cta & 63) * 4;
        const float* Wi = dir ? eWi_b : eWi_f;
        const float* Wh = dir ? eWh_b : eWh_f;
        const float* bb = dir ? eb_b  : eb_f;
        const int u = warp >> 2, gg = warp & 3;
        const int row = gg * E + (ubase + u);
        const float4* wi4 = (const float4*)(Wi + (size_t)row * E);
        const float4* wh4 = (const float4*)(Wh + (size_t)row * E);
        const float brow = __ldg(bb + row);
        for (int t = 0; t < S; t++) {
            const int xt = dir ? (S - 1 - t) : t;
            const float* hrd = dir ? g_ehb[(t ^ 1) & 1] : g_ehf[(t ^ 1) & 1];
            if (tid < E) { s_a[tid] = g_emb[xt * E + tid]; s_b[tid] = hrd[tid]; }
            __syncthreads();
            const float4* a4 = (const float4*)s_a;
            const float4* b4 = (const float4*)s_b;
            float acc = 0.f;
            #pragma unroll
            for (int i = 0; i < 2; i++) {
                float4 w = __ldg(wi4 + lane + 32 * i); float4 v = a4[lane + 32 * i];
                acc += w.x*v.x + w.y*v.y + w.z*v.z + w.w*v.w;
                float4 w2 = __ldg(wh4 + lane + 32 * i); float4 v2 = b4[lane + 32 * i];
                acc += w2.x*v2.x + w2.y*v2.y + w2.z*v2.z + w2.w*v2.w;
            }
            #pragma unroll
            for (int o = 16; o; o >>= 1) acc += __shfl_down_sync(0xffffffffu, acc, o);
            if (lane == 0) s_red[warp] = acc + brow;
            __syncthreads();
            if (tid < 4) {
                float gi = s_red[tid*4+0], gf = s_red[tid*4+1], gc = s_red[tid*4+2], go = s_red[tid*4+3];
                float c = sigf(gf) * s_ec[tid] + sigf(gi) * tanhf(gc);
                float h = sigf(go) * tanhf(c);
                s_ec[tid] = c;
                int uj = ubase + tid;
                (dir ? g_ehb[t & 1] : g_ehf[t & 1])[uj] = h;
                (dir ? g_outb : g_outf)[xt * E + uj]   = h;
            }
            gbar_n(&g_eA[dir], &g_eR[dir], 64u);
        }
    }
    gbar();

    // ---------- setup2: encT, A, dvec, enc_hidden ----------
    for (int idx = cta * NT + tid; idx < H2 * S; idx += GRID * NT) {
        int k = idx / S, s = idx - k * S;
        float v = (k < E) ? g_outf[s * E + k] : g_outb[s * E + (k - E)];
        g_encT[idx] = g_mask[s] ? v : 0.f;
    }
    for (int s = cta; s < S; s += GRID) {
        float m = g_mask[s] ? 1.f : 0.f;
        for (int j = tid; j < H2; j += NT)
            s_b[j] = ((j < E) ? g_outf[s * E + j] : g_outb[s * E + j - E]) * m;
        __syncthreads();
        if (tid < H2) {
            const int k = tid;
            float acc = 0.f;
            #pragma unroll 4
            for (int j = 0; j < H2; j++) acc += s_b[j] * __ldg(attn_W + j * H2 + k);
            g_A[s * H2 + k] = acc;
        }
        if (tid == 0) {
            float acc = 0.f;
            for (int j = 0; j < H2; j++) acc += s_b[j] * __ldg(attn_b + j);
            g_dvec[s] = acc;
        }
        __syncthreads();
    }
    if (cta == 0) {
        for (int j = tid; j < E; j += NT) {
            float hf = g_outf[(S - 1) * E + j];
            float hb = g_outb[0 * E + j];
            g_enchid[j]     = hf; g_enchid[E + j] = hb;
            g_dh[1][j]      = hf; g_dh[1][E + j]  = hb;
        }
        if (tid == 0 && sent_off) out[0] = 1.0f;   // SOS
    }
    if (tid == 0) s_word = 1;                       // SOS
    gbar();

    // ---------- autoregressive decode, 512 steps ----------
    for (int t = 0; t < S; t++) {
        // Phase G: decoder LSTM (CTAs 0..127, warp-per-row)
        if (cta < 128) {
            const int w = s_word;
            if (tid < H2) {
                s_a[tid]      = fmaxf(__ldg(dec_emb + (size_t)w * H2 + tid), 0.f);
                s_a[H2 + tid] = g_enchid[tid];
                s_b[tid]      = g_dh[(t ^ 1) & 1][tid];
            }
            __syncthreads();
            const int u = warp >> 2, gg = warp & 3;
            const int row = gg * H2 + (cta * 4 + u);
            const float4* wi4 = (const float4*)(dWi + (size_t)row * HC);
            const float4* wh4 = (const float4*)(dWh + (size_t)row * H2);
            const float4* a4 = (const float4*)s_a;
            const float4* b4 = (const float4*)s_b;
            float acc = 0.f;
            #pragma unroll
            for (int i = 0; i < 8; i++) {
                float4 wv = __ldg(wi4 + lane + 32 * i); float4 av = a4[lane + 32 * i];
                acc += wv.x*av.x + wv.y*av.y + wv.z*av.z + wv.w*av.w;
            }
            #pragma unroll
            for (int i = 0; i < 4; i++) {
                float4 wv = __ldg(wh4 + lane + 32 * i); float4 bv = b4[lane + 32 * i];
                acc += wv.x*bv.x + wv.y*bv.y + wv.z*bv.z + wv.w*bv.w;
            }
            #pragma unroll
            for (int o = 16; o; o >>= 1) acc += __shfl_down_sync(0xffffffffu, acc, o);
            if (lane == 0) s_red[warp] = acc + __ldg(db + row);
            __syncthreads();
            if (tid < 4) {
                float gi = s_red[tid*4+0], gf = s_red[tid*4+1], gc = s_red[tid*4+2], go = s_red[tid*4+3];
                float c = sigf(gf) * s_dc[tid] + sigf(gi) * tanhf(gc);
                float h = sigf(go) * tanhf(c);
                s_dc[tid] = c;
                g_dh[t & 1][cta * 4 + tid] = h;
            }
        }
        gbar();

        // Phase S: scores = A @ h + d  (CTAs 0..31, warp-per-score)
        if (cta < 32) {
            const int gw = cta * 16 + warp;
            const float4* Ar4 = (const float4*)(g_A + (size_t)gw * H2);
            const float4* hv4 = (const float4*)(g_dh[t & 1]);
            float acc = 0.f;
            #pragma unroll
            for (int i = 0; i < 4; i++) {
                float4 a = __ldg(Ar4 + lane + 32 * i);
                float4 h = hv4[lane + 32 * i];
                acc += a.x*h.x + a.y*h.y + a.z*h.z + a.w*h.w;
            }
            #pragma unroll
            for (int o = 16; o; o >>= 1) acc += __shfl_down_sync(0xffffffffu, acc, o);
            if (lane == 0) {
                float sc = acc + g_dvec[gw];
                g_scores[gw] = g_mask[gw] ? sc : -INFINITY;
            }
        }
        gbar();

        // Phase C: redundant softmax + context (CTAs 0..31)
        if (cta < 32) {
            s_b[tid] = g_scores[tid];
            __syncthreads();
            float m = s_b[tid];
            #pragma unroll
            for (int o = 16; o; o >>= 1) m = fmaxf(m, __shfl_down_sync(0xffffffffu, m, o));
            if (lane == 0) s_red[warp] = m;
            __syncthreads();
            if (tid == 0) {
                float mm = s_red[0];
                #pragma unroll
                for (int i = 1; i < 16; i++) mm = fmaxf(mm, s_red[i]);
                s_red[16] = mm;
            }
            __syncthreads();
            const float mx = s_red[16];
            float e = (mx == -INFINITY) ? 0.f : expf(s_b[tid] - mx);
            float sum = e;
            #pragma unroll
            for (int o = 16; o; o >>= 1) sum += __shfl_down_sync(0xffffffffu, sum, o);
            if (lane == 0) s_red[warp] = sum;
            __syncthreads();
            if (tid == 0) {
                float ss = 0.f;
                #pragma unroll
                for (int i = 0; i < 16; i++) ss += s_red[i];
                s_red[17] = (ss > 0.f) ? 1.f / ss : 0.f;
            }
            __syncthreads();
            s_b[tid] = e * s_red[17];
            __syncthreads();
            const int gw = cta * 16 + warp;               // 0..511
            const float4* et4 = (const float4*)(g_encT + (size_t)gw * S);
            const float4* w4  = (const float4*)s_b;
            float acc = 0.f;
            #pragma unroll
            for (int i = 0; i < 4; i++) {
                float4 ev = __ldg(et4 + lane + 32 * i);
                float4 wv = w4[lane + 32 * i];
                acc += ev.x*wv.x + ev.y*wv.y + ev.z*wv.z + ev.w*wv.w;
            }
            #pragma unroll
            for (int o = 16; o; o >>= 1) acc += __shfl_down_sync(0xffffffffu, acc, o);
            if (lane == 0) g_ctx[gw] = acc;
        }
        gbar();

        // Phase Z: z = [h, ctx] @ W_W^T + W_b  (CTAs 0..63, warp-per-row)
        if (cta < 64) {
            if (tid < H2) {
                s_a[tid]      = g_dh[t & 1][tid];
                s_a[H2 + tid] = g_ctx[tid];
            }
            __syncthreads();
            const int gw = cta * 16 + warp;               // 0..1023
            const float4* ww4 = (const float4*)(W_W + (size_t)gw * HC);
            const float4* a4  = (const float4*)s_a;
            float acc = 0.f;
            #pragma unroll
            for (int i = 0; i < 8; i++) {
                float4 w = __ldg(ww4 + lane + 32 * i);
                float4 v = a4[lane + 32 * i];
                acc += w.x*v.x + w.y*v.y + w.z*v.z + w.w*v.w;
            }
            #pragma unroll
            for (int o = 16; o; o >>= 1) acc += __shfl_down_sync(0xffffffffu, acc, o);
            if (lane == 0) g_z[gw] = acc + __ldg(W_b + gw);
        }
        gbar();

        // Phase L: logits via blocked-transposed g_linT (warp owns k-range of 64)
        {
            for (int i = tid; i < HC; i += NT) s_a[i] = g_z[i];
            __syncthreads();
            const float* wb = g_linT + (size_t)cta * (1024 * CPAD) + (size_t)(warp * 64) * CPAD;
            const float* zw = s_a + warp * 64;
            const bool third = lane < 24;
            float4 a0 = make_float4(0,0,0,0), a1 = a0, a2 = a0;
            if (cta < RES_BLKS) linT_dot<0>(wb, zw, lane, third, a0, a1, a2);
            else                linT_dot<1>(wb, zw, lane, third, a0, a1, a2);
            float4* sp = (float4*)(s_part + warp * CPAD);
            sp[lane] = a0; sp[lane + 32] = a1;
            if (third) sp[lane + 64] = a2;
            __syncthreads();
            const int base = cta * CBLK;
            const int ncol = min(CBLK, VOCAB - base);
            float bv = -INFINITY; int bi = 0x7fffffff;
            float* olog = out_logits + (size_t)t * VOCAB;
            if (tid < ncol) {
                float sum = 0.f;
                #pragma unroll
                for (int w = 0; w < 16; w++) sum += s_part[w * CPAD + tid];
                float v = sum + __ldg(lin_b + base + tid);
                __stcs(olog + base + tid, v);
                bv = v; bi = base + tid;
            }
            #pragma unroll
            for (int o = 16; o; o >>= 1) {
                float ov = __shfl_down_sync(0xffffffffu, bv, o);
                int   oi = __shfl_down_sync(0xffffffffu, bi, o);
                if (ov > bv || (ov == bv && oi < bi)) { bv = ov; bi = oi; }
            }
            if (lane == 0) { s_rv[warp] = bv; s_ri[warp] = bi; }
            __syncthreads();
            if (warp == 0) {
                float v = (lane < 16) ? s_rv[lane] : -INFINITY;
                int  ii = (lane < 16) ? s_ri[lane] : 0x7fffffff;
                #pragma unroll
                for (int o = 8; o; o >>= 1) {
                    float ov = __shfl_down_sync(0xffffffffu, v, o);
                    int   oi = __shfl_down_sync(0xffffffffu, ii, o);
                    if (ov > v || (ov == v && oi < ii)) { v = ov; ii = oi; }
                }
                if (lane == 0) { g_pval[cta] = v; g_pidx[cta] = ii; }
            }
        }
        gbar();

        // Phase R: warp-parallel global argmax -> next word
        if (warp == 0) {
            float v = -INFINITY; int ii = 0x7fffffff;
            #pragma unroll
            for (int i = 0; i < 5; i++) {
                int idx = lane + 32 * i;
                if (idx < GRID) {
                    float pv = g_pval[idx]; int pi = g_pidx[idx];
                    if (pv > v || (pv == v && pi < ii)) { v = pv; ii = pi; }
                }
            }
            #pragma unroll
            for (int o = 16; o; o >>= 1) {
                float ov = __shfl_down_sync(0xffffffffu, v, o);
                int   oi = __shfl_down_sync(0xffffffffu, ii, o);
                if (ov > v || (ov == v && oi < ii)) { v = ov; ii = oi; }
            }
            if (lane == 0) {
                s_word = ii;
                if (cta == 0 && sent_off) out[1 + t] = (float)ii;
            }
        }
        __syncthreads();
    }
}

extern "C" void kernel_launch(void* const* d_in, const int* in_sizes, int n_in,
                              void* d_out, int out_size)
{
    const int*   tokens  = (const int*)  d_in[0];
    const float* enc_emb = (const float*)d_in[2];
    const float* dec_emb = (const float*)d_in[3];
    const float* eWi_f   = (const float*)d_in[4];
    const float* eWh_f   = (const float*)d_in[5];
    const float* eb_f    = (const float*)d_in[6];
    const float* eWi_b   = (const float*)d_in[7];
    const float* eWh_b   = (const float*)d_in[8];
    const float* eb_b    = (const float*)d_in[9];
    const float* dWi     = (const float*)d_in[10];
    const float* dWh     = (const float*)d_in[11];
    const float* db      = (const float*)d_in[12];
    const float* attn_W  = (const float*)d_in[13];
    const float* attn_b  = (const float*)d_in[14];
    const float* W_W     = (const float*)d_in[15];
    const float* W_b     = (const float*)d_in[16];
    const float* lin_W   = (const float*)d_in[17];
    const float* lin_b   = (const float*)d_in[18];

    long long need_full = (long long)(S + 1) + (long long)S * VOCAB;
    int sent_off = ((long long)out_size >= need_full) ? 1 : 0;

    seq2seq_kernel<<<GRID, NT>>>(tokens, enc_emb, dec_emb,
                                 eWi_f, eWh_f, eb_f, eWi_b, eWh_b, eb_b,
                                 dWi, dWh, db, attn_W, attn_b, W_W, W_b,
                                 lin_W, lin_b, (float*)d_out, sent_off);
}

// round 7
// speedup vs baseline: 1.7147x; 1.0978x over previous
#include <cuda_runtime.h>
#include <math.h>

#define S     512
#define E     256
#define H2    512
#define HC    1024
#define VOCAB 50257
#define GRID  148
#define NT    512
#define CBLK  340            // vocab cols per CTA block
#define CPAD  352            // padded row stride (floats)
#define PF_ROWS 28           // rows per warp-chunk prefetched into L2 during idle phases

// ---------------- device scratch (static globals; no allocation) ----------------
__device__ float g_linT[(size_t)GRID * 1024 * CPAD];   // blocked transposed lin_W (~213MB)
__device__ float g_emb[S*E];
__device__ int   g_mask[S];
__device__ float g_ehf[2][E];
__device__ float g_ehb[2][E];
__device__ float g_outf[S*E];
__device__ float g_outb[S*E];
__device__ float g_encT[H2*S];
__device__ float g_A[S*H2];
__device__ float g_dvec[S];
__device__ float g_enchid[H2];
__device__ float g_dh[2][H2];
__device__ float g_scores[S];
__device__ float g_ctx[H2];
__device__ float g_z[HC];
__device__ float g_pval[GRID];
__device__ int   g_pidx[GRID];
// generation-counting barriers: monotonic, replay-safe (A = gen*N, R = gen at launch exit)
__device__ unsigned long long g_bA, g_bR;
__device__ unsigned long long g_eA[2], g_eR[2];

__device__ __forceinline__ float sigf(float x) { return 1.f / (1.f + expf(-x)); }

__device__ __forceinline__ void gbar_n(unsigned long long* A, unsigned long long* R, unsigned n) {
    __syncthreads();
    if (threadIdx.x == 0) {
        __threadfence();
        unsigned long long pos = atomicAdd(A, 1ULL);
        unsigned long long gen = pos / n;
        if (pos - gen * n == n - 1ULL) {
            __threadfence();
            atomicAdd(R, 1ULL);
        } else {
            unsigned long long r;
            do { asm volatile("ld.acquire.gpu.u64 %0, [%1];" : "=l"(r) : "l"(R) : "memory"); } while (r <= gen);
        }
    }
    __syncthreads();
}
__device__ __forceinline__ void gbar() { gbar_n(&g_bA, &g_bR, GRID); }

__device__ __forceinline__ void fma4(float4& a, const float4& c, float s) {
    a.x = fmaf(s, c.x, a.x); a.y = fmaf(s, c.y, a.y);
    a.z = fmaf(s, c.z, a.z); a.w = fmaf(s, c.w, a.w);
}

// Prefetch the first PF_ROWS of this warp's 64-row k-chunk into L2 (non-blocking).
__device__ __forceinline__ void prefetch_slab(const float* slab, int warp, int lane) {
    const char* base = (const char*)(slab + (size_t)(warp * 64) * CPAD);
    const int lines = PF_ROWS * 11;            // 11 x 128B lines per CPAD row
    #pragma unroll 4
    for (int i = lane; i < lines; i += 32)
        asm volatile("prefetch.global.L2 [%0];" :: "l"(base + (size_t)i * 128));
}

// Phase L inner GEMV over one warp's 64 k-rows, depth-2 software pipeline, streaming loads.
__device__ __forceinline__ void linT_dot(const float* wb, const float* zw, int lane, bool third,
                                         float4& a0, float4& a1, float4& a2)
{
    const float4 zf = make_float4(0.f, 0.f, 0.f, 0.f);
    const float4* r0 = (const float4*)wb;
    const float4* r1 = (const float4*)(wb + CPAD);
    float4 b00 = __ldcs(r0 + lane), b01 = __ldcs(r0 + lane + 32), b02 = third ? __ldcs(r0 + lane + 64) : zf;
    float4 b10 = __ldcs(r1 + lane), b11 = __ldcs(r1 + lane + 32), b12 = third ? __ldcs(r1 + lane + 64) : zf;
    #pragma unroll 1
    for (int k = 0; k < 62; k += 2) {
        const float4* rn = (const float4*)(wb + (k + 2) * CPAD);
        float4 n00 = __ldcs(rn + lane), n01 = __ldcs(rn + lane + 32), n02 = third ? __ldcs(rn + lane + 64) : zf;
        float z0 = zw[k];
        fma4(a0, b00, z0); fma4(a1, b01, z0); fma4(a2, b02, z0);
        b00 = n00; b01 = n01; b02 = n02;
        const float4* rm = (const float4*)(wb + (k + 3) * CPAD);
        float4 n10 = __ldcs(rm + lane), n11 = __ldcs(rm + lane + 32), n12 = third ? __ldcs(rm + lane + 64) : zf;
        float z1 = zw[k + 1];
        fma4(a0, b10, z1); fma4(a1, b11, z1); fma4(a2, b12, z1);
        b10 = n10; b11 = n11; b12 = n12;
    }
    float z0 = zw[62];
    fma4(a0, b00, z0); fma4(a1, b01, z0); fma4(a2, b02, z0);
    float z1 = zw[63];
    fma4(a0, b10, z1); fma4(a1, b11, z1); fma4(a2, b12, z1);
}

__global__ void __launch_bounds__(NT, 1) seq2seq_kernel(
    const int*   __restrict__ tokens,
    const float* __restrict__ enc_emb,
    const float* __restrict__ dec_emb,
    const float* __restrict__ eWi_f, const float* __restrict__ eWh_f, const float* __restrict__ eb_f,
    const float* __restrict__ eWi_b, const float* __restrict__ eWh_b, const float* __restrict__ eb_b,
    const float* __restrict__ dWi,   const float* __restrict__ dWh,   const float* __restrict__ db,
    const float* __restrict__ attn_W, const float* __restrict__ attn_b,
    const float* __restrict__ W_W,    const float* __restrict__ W_b,
    const float* __restrict__ lin_W,  const float* __restrict__ lin_b,
    float* __restrict__ out, int sent_off)
{
    __shared__ float s_a[HC];            // 4KB
    __shared__ float s_b[H2];            // 2KB
    __shared__ float s_part[16 * CPAD];  // 22.5KB (also reused as transpose tile)
    __shared__ float s_rv[16];
    __shared__ int   s_ri[16];
    __shared__ float s_red[32];
    __shared__ float s_ec[4];
    __shared__ float s_dc[4];
    __shared__ int   s_word;

    const int cta = blockIdx.x, tid = threadIdx.x;
    const int warp = tid >> 5, lane = tid & 31;
    float* out_logits = out + (sent_off ? (S + 1) : 0);
    const float* myslab = g_linT + (size_t)cta * (1024 * CPAD);

    // ---------- phase T: transpose own lin_W block into g_linT ----------
    {
        float (*tile)[33] = (float (*)[33])s_part;   // 32x33
        const int x = lane, y = warp;                // y: 0..15
        float* dst = g_linT + (size_t)cta * (1024 * CPAD);
        for (int kt = 0; kt < 1024; kt += 32) {
            for (int ct = 0; ct < CPAD; ct += 32) {
                #pragma unroll
                for (int yy = 0; yy < 2; yy++) {
                    int c   = ct + y + 16 * yy;
                    int row = cta * CBLK + c;
                    float v = 0.f;
                    if (c < CBLK && row < VOCAB) v = __ldg(lin_W + (size_t)row * HC + kt + x);
                    tile[y + 16 * yy][x] = v;
                }
                __syncthreads();
                #pragma unroll
                for (int yy = 0; yy < 2; yy++) {
                    int k = kt + y + 16 * yy;
                    dst[(size_t)k * CPAD + ct + x] = tile[x][y + 16 * yy];
                }
                __syncthreads();
            }
        }
    }

    // ---------- setup ----------
    for (int idx = cta * NT + tid; idx < S * E; idx += GRID * NT) {
        int t = idx / E, k = idx - t * E;
        g_emb[idx] = fmaxf(__ldg(enc_emb + (size_t)tokens[t] * E + k), 0.f);
    }
    for (int idx = cta * NT + tid; idx < S; idx += GRID * NT) g_mask[idx] = tokens[idx] > 0;
    for (int idx = cta * NT + tid; idx < E; idx += GRID * NT) { g_ehf[1][idx] = 0.f; g_ehb[1][idx] = 0.f; }
    if (tid < 4) { s_ec[tid] = 0.f; s_dc[tid] = 0.f; }
    gbar();

    // ---------- encoder BiLSTM: CTAs 0..63 fwd, 64..127 bwd ----------
    if (cta < 128) {
        const int dir   = cta >> 6;
        const int ubase = (cta & 63) * 4;
        const float* Wi = dir ? eWi_b : eWi_f;
        const float* Wh = dir ? eWh_b : eWh_f;
        const float* bb = dir ? eb_b  : eb_f;
        const int u = warp >> 2, gg = warp & 3;
        const int row = gg * E + (ubase + u);
        const float4* wi4 = (const float4*)(Wi + (size_t)row * E);
        const float4* wh4 = (const float4*)(Wh + (size_t)row * E);
        const float brow = __ldg(bb + row);
        for (int t = 0; t < S; t++) {
            const int xt = dir ? (S - 1 - t) : t;
            const float* hrd = dir ? g_ehb[(t ^ 1) & 1] : g_ehf[(t ^ 1) & 1];
            if (tid < E) { s_a[tid] = g_emb[xt * E + tid]; s_b[tid] = hrd[tid]; }
            __syncthreads();
            const float4* a4 = (const float4*)s_a;
            const float4* b4 = (const float4*)s_b;
            float acc = 0.f;
            #pragma unroll
            for (int i = 0; i < 2; i++) {
                float4 w = __ldg(wi4 + lane + 32 * i); float4 v = a4[lane + 32 * i];
                acc += w.x*v.x + w.y*v.y + w.z*v.z + w.w*v.w;
                float4 w2 = __ldg(wh4 + lane + 32 * i); float4 v2 = b4[lane + 32 * i];
                acc += w2.x*v2.x + w2.y*v2.y + w2.z*v2.z + w2.w*v2.w;
            }
            #pragma unroll
            for (int o = 16; o; o >>= 1) acc += __shfl_down_sync(0xffffffffu, acc, o);
            if (lane == 0) s_red[warp] = acc + brow;
            __syncthreads();
            if (tid < 4) {
                float gi = s_red[tid*4+0], gf = s_red[tid*4+1], gc = s_red[tid*4+2], go = s_red[tid*4+3];
                float c = sigf(gf) * s_ec[tid] + sigf(gi) * tanhf(gc);
                float h = sigf(go) * tanhf(c);
                s_ec[tid] = c;
                int uj = ubase + tid;
                (dir ? g_ehb[t & 1] : g_ehf[t & 1])[uj] = h;
                (dir ? g_outb : g_outf)[xt * E + uj]   = h;
            }
            gbar_n(&g_eA[dir], &g_eR[dir], 64u);
        }
    }
    gbar();

    // ---------- setup2: encT, A, dvec, enc_hidden ----------
    for (int idx = cta * NT + tid; idx < H2 * S; idx += GRID * NT) {
        int k = idx / S, s = idx - k * S;
        float v = (k < E) ? g_outf[s * E + k] : g_outb[s * E + (k - E)];
        g_encT[idx] = g_mask[s] ? v : 0.f;
    }
    for (int s = cta; s < S; s += GRID) {
        float m = g_mask[s] ? 1.f : 0.f;
        for (int j = tid; j < H2; j += NT)
            s_b[j] = ((j < E) ? g_outf[s * E + j] : g_outb[s * E + j - E]) * m;
        __syncthreads();
        if (tid < H2) {
            const int k = tid;
            float acc = 0.f;
            #pragma unroll 4
            for (int j = 0; j < H2; j++) acc += s_b[j] * __ldg(attn_W + j * H2 + k);
            g_A[s * H2 + k] = acc;
        }
        if (tid == 0) {
            float acc = 0.f;
            for (int j = 0; j < H2; j++) acc += s_b[j] * __ldg(attn_b + j);
            g_dvec[s] = acc;
        }
        __syncthreads();
    }
    if (cta == 0) {
        for (int j = tid; j < E; j += NT) {
            float hf = g_outf[(S - 1) * E + j];
            float hb = g_outb[0 * E + j];
            g_enchid[j]     = hf; g_enchid[E + j] = hb;
            g_dh[1][j]      = hf; g_dh[1][E + j]  = hb;
        }
        if (tid == 0 && sent_off) out[0] = 1.0f;   // SOS
    }
    if (tid == 0) s_word = 1;                       // SOS
    gbar();

    // ---------- autoregressive decode, 512 steps ----------
    for (int t = 0; t < S; t++) {
        // Phase G: decoder LSTM (CTAs 0..127, warp-per-row)
        if (cta < 128) {
            const int w = s_word;
            if (tid < H2) {
                s_a[tid]      = fmaxf(__ldg(dec_emb + (size_t)w * H2 + tid), 0.f);
                s_a[H2 + tid] = g_enchid[tid];
                s_b[tid]      = g_dh[(t ^ 1) & 1][tid];
            }
            __syncthreads();
            const int u = warp >> 2, gg = warp & 3;
            const int row = gg * H2 + (cta * 4 + u);
            const float4* wi4 = (const float4*)(dWi + (size_t)row * HC);
            const float4* wh4 = (const float4*)(dWh + (size_t)row * H2);
            const float4* a4 = (const float4*)s_a;
            const float4* b4 = (const float4*)s_b;
            float acc = 0.f;
            #pragma unroll
            for (int i = 0; i < 8; i++) {
                float4 wv = __ldg(wi4 + lane + 32 * i); float4 av = a4[lane + 32 * i];
                acc += wv.x*av.x + wv.y*av.y + wv.z*av.z + wv.w*av.w;
            }
            #pragma unroll
            for (int i = 0; i < 4; i++) {
                float4 wv = __ldg(wh4 + lane + 32 * i); float4 bv = b4[lane + 32 * i];
                acc += wv.x*bv.x + wv.y*bv.y + wv.z*bv.z + wv.w*bv.w;
            }
            #pragma unroll
            for (int o = 16; o; o >>= 1) acc += __shfl_down_sync(0xffffffffu, acc, o);
            if (lane == 0) s_red[warp] = acc + __ldg(db + row);
            __syncthreads();
            if (tid < 4) {
                float gi = s_red[tid*4+0], gf = s_red[tid*4+1], gc = s_red[tid*4+2], go = s_red[tid*4+3];
                float c = sigf(gf) * s_dc[tid] + sigf(gi) * tanhf(gc);
                float h = sigf(go) * tanhf(c);
                s_dc[tid] = c;
                g_dh[t & 1][cta * 4 + tid] = h;
            }
        }
        // Prefetch own slab prefix into L2; drains during S/C/Z while DRAM is otherwise idle.
        prefetch_slab(myslab, warp, lane);
        gbar();

        // Phase S: scores = A @ h + d  (CTAs 0..31, warp-per-score)
        if (cta < 32) {
            const int gw = cta * 16 + warp;
            const float4* Ar4 = (const float4*)(g_A + (size_t)gw * H2);
            const float4* hv4 = (const float4*)(g_dh[t & 1]);
            float acc = 0.f;
            #pragma unroll
            for (int i = 0; i < 4; i++) {
                float4 a = __ldg(Ar4 + lane + 32 * i);
                float4 h = hv4[lane + 32 * i];
                acc += a.x*h.x + a.y*h.y + a.z*h.z + a.w*h.w;
            }
            #pragma unroll
            for (int o = 16; o; o >>= 1) acc += __shfl_down_sync(0xffffffffu, acc, o);
            if (lane == 0) {
                float sc = acc + g_dvec[gw];
                g_scores[gw] = g_mask[gw] ? sc : -INFINITY;
            }
        }
        gbar();

        // Phase C: redundant softmax + context (CTAs 0..31)
        if (cta < 32) {
            s_b[tid] = g_scores[tid];
            __syncthreads();
            float m = s_b[tid];
            #pragma unroll
            for (int o = 16; o; o >>= 1) m = fmaxf(m, __shfl_down_sync(0xffffffffu, m, o));
            if (lane == 0) s_red[warp] = m;
            __syncthreads();
            if (tid == 0) {
                float mm = s_red[0];
                #pragma unroll
                for (int i = 1; i < 16; i++) mm = fmaxf(mm, s_red[i]);
                s_red[16] = mm;
            }
            __syncthreads();
            const float mx = s_red[16];
            float e = (mx == -INFINITY) ? 0.f : expf(s_b[tid] - mx);
            float sum = e;
            #pragma unroll
            for (int o = 16; o; o >>= 1) sum += __shfl_down_sync(0xffffffffu, sum, o);
            if (lane == 0) s_red[warp] = sum;
            __syncthreads();
            if (tid == 0) {
                float ss = 0.f;
                #pragma unroll
                for (int i = 0; i < 16; i++) ss += s_red[i];
                s_red[17] = (ss > 0.f) ? 1.f / ss : 0.f;
            }
            __syncthreads();
            s_b[tid] = e * s_red[17];
            __syncthreads();
            const int gw = cta * 16 + warp;               // 0..511
            const float4* et4 = (const float4*)(g_encT + (size_t)gw * S);
            const float4* w4  = (const float4*)s_b;
            float acc = 0.f;
            #pragma unroll
            for (int i = 0; i < 4; i++) {
                float4 ev = __ldg(et4 + lane + 32 * i);
                float4 wv = w4[lane + 32 * i];
                acc += ev.x*wv.x + ev.y*wv.y + ev.z*wv.z + ev.w*wv.w;
            }
            #pragma unroll
            for (int o = 16; o; o >>= 1) acc += __shfl_down_sync(0xffffffffu, acc, o);
            if (lane == 0) g_ctx[gw] = acc;
        }
        gbar();

        // Phase Z: z = [h, ctx] @ W_W^T + W_b  (CTAs 0..63, warp-per-row)
        if (cta < 64) {
            if (tid < H2) {
                s_a[tid]      = g_dh[t & 1][tid];
                s_a[H2 + tid] = g_ctx[tid];
            }
            __syncthreads();
            const int gw = cta * 16 + warp;               // 0..1023
            const float4* ww4 = (const float4*)(W_W + (size_t)gw * HC);
            const float4* a4  = (const float4*)s_a;
            float acc = 0.f;
            #pragma unroll
            for (int i = 0; i < 8; i++) {
                float4 w = __ldg(ww4 + lane + 32 * i);
                float4 v = a4[lane + 32 * i];
                acc += w.x*v.x + w.y*v.y + w.z*v.z + w.w*v.w;
            }
            #pragma unroll
            for (int o = 16; o; o >>= 1) acc += __shfl_down_sync(0xffffffffu, acc, o);
            if (lane == 0) g_z[gw] = acc + __ldg(W_b + gw);
        }
        gbar();

        // Phase L: logits via blocked-transposed g_linT (warp owns k-range of 64)
        {
            for (int i = tid; i < HC; i += NT) s_a[i] = g_z[i];
            __syncthreads();
            const float* wb = myslab + (size_t)(warp * 64) * CPAD;
            const float* zw = s_a + warp * 64;
            const bool third = lane < 21;                 // 85 float4 = 340 cols (skip pad)
            float4 a0 = make_float4(0,0,0,0), a1 = a0, a2 = a0;
            linT_dot(wb, zw, lane, third, a0, a1, a2);
            float4* sp = (float4*)(s_part + warp * CPAD);
            sp[lane] = a0; sp[lane + 32] = a1;
            if (third) sp[lane + 64] = a2;
            __syncthreads();
            const int base = cta * CBLK;
            const int ncol = min(CBLK, VOCAB - base);
            float bv = -INFINITY; int bi = 0x7fffffff;
            float* olog = out_logits + (size_t)t * VOCAB;
            if (tid < ncol) {
                float sum = 0.f;
                #pragma unroll
                for (int w = 0; w < 16; w++) sum += s_part[w * CPAD + tid];
                float v = sum + __ldg(lin_b + base + tid);
                __stcs(olog + base + tid, v);
                bv = v; bi = base + tid;
            }
            #pragma unroll
            for (int o = 16; o; o >>= 1) {
                float ov = __shfl_down_sync(0xffffffffu, bv, o);
                int   oi = __shfl_down_sync(0xffffffffu, bi, o);
                if (ov > bv || (ov == bv && oi < bi)) { bv = ov; bi = oi; }
            }
            if (lane == 0) { s_rv[warp] = bv; s_ri[warp] = bi; }
            __syncthreads();
            if (warp == 0) {
                float v = (lane < 16) ? s_rv[lane] : -INFINITY;
                int  ii = (lane < 16) ? s_ri[lane] : 0x7fffffff;
                #pragma unroll
                for (int o = 8; o; o >>= 1) {
                    float ov = __shfl_down_sync(0xffffffffu, v, o);
                    int   oi = __shfl_down_sync(0xffffffffu, ii, o);
                    if (ov > v || (ov == v && oi < ii)) { v = ov; ii = oi; }
                }
                if (lane == 0) { g_pval[cta] = v; g_pidx[cta] = ii; }
            }
        }
        gbar();

        // Phase R: warp-parallel global argmax -> next word
        if (warp == 0) {
            float v = -INFINITY; int ii = 0x7fffffff;
            #pragma unroll
            for (int i = 0; i < 5; i++) {
                int idx = lane + 32 * i;
                if (idx < GRID) {
                    float pv = g_pval[idx]; int pi = g_pidx[idx];
                    if (pv > v || (pv == v && pi < ii)) { v = pv; ii = pi; }
                }
            }
            #pragma unroll
            for (int o = 16; o; o >>= 1) {
                float ov = __shfl_down_sync(0xffffffffu, v, o);
                int   oi = __shfl_down_sync(0xffffffffu, ii, o);
                if (ov > v || (ov == v && oi < ii)) { v = ov; ii = oi; }
            }
            if (lane == 0) {
                s_word = ii;
                if (cta == 0 && sent_off) out[1 + t] = (float)ii;
            }
        }
        __syncthreads();
    }
}

extern "C" void kernel_launch(void* const* d_in, const int* in_sizes, int n_in,
                              void* d_out, int out_size)
{
    const int*   tokens  = (const int*)  d_in[0];
    const float* enc_emb = (const float*)d_in[2];
    const float* dec_emb = (const float*)d_in[3];
    const float* eWi_f   = (const float*)d_in[4];
    const float* eWh_f   = (const float*)d_in[5];
    const float* eb_f    = (const float*)d_in[6];
    const float* eWi_b   = (const float*)d_in[7];
    const float* eWh_b   = (const float*)d_in[8];
    const float* eb_b    = (const float*)d_in[9];
    const float* dWi     = (const float*)d_in[10];
    const float* dWh     = (const float*)d_in[11];
    const float* db      = (const float*)d_in[12];
    const float* attn_W  = (const float*)d_in[13];
    const float* attn_b  = (const float*)d_in[14];
    const float* W_W     = (const float*)d_in[15];
    const float* W_b     = (const float*)d_in[16];
    const float* lin_W   = (const float*)d_in[17];
    const float* lin_b   = (const float*)d_in[18];

    long long need_full = (long long)(S + 1) + (long long)S * VOCAB;
    int sent_off = ((long long)out_size >= need_full) ? 1 : 0;

    seq2seq_kernel<<<GRID, NT>>>(tokens, enc_emb, dec_emb,
                                 eWi_f, eWh_f, eb_f, eWi_b, eWh_b, eb_b,
                                 dWi, dWh, db, attn_W, attn_b, W_W, W_b,
                                 lin_W, lin_b, (float*)d_out, sent_off);
}